// round 12
// baseline (speedup 1.0000x reference)
#include <cuda_runtime.h>
#include <cuda_bf16.h>
#include <math.h>
#include <stdint.h>

#define DIM 256
#define NTOT 100000
#define ETRI 400000
#define NVALMAX 100000
#define NATTMAX 1001
#define KPAD_VAL 320
#define MT_S 40   // smem row stride in bf16 (80B): conflict-free for ldmatrix 8-row phases

// ---------------- scratch ----------------
__device__ float g_valW[NVALMAX * DIM];
__device__ float g_attW[NATTMAX * DIM];
__device__ float g_attdot[NATTMAX];
__device__ float g_entdot[NTOT];
__device__ float g_p[ETRI];
__device__ int   g_cnt[NTOT];
__device__ int   g_ptr[NTOT + 1];
__device__ int   g_eptr[NTOT + 1];
__device__ int   g_fill[NTOT];
__device__ int   g_idx[ETRI];
__device__ int   g_bsum[128];
__device__ int   g_boff[128];
__device__ float g_F1[NTOT * DIM];
__device__ float g_F2[NTOT * DIM];
__device__ __nv_bfloat16 g_xa_h[NTOT * DIM];
__device__ __nv_bfloat16 g_xa_l[NTOT * DIM];
__device__ __nv_bfloat16 g_wet_h[DIM * KPAD_VAL];
__device__ __nv_bfloat16 g_wet_l[DIM * KPAD_VAL];
__device__ __nv_bfloat16 g_w1t_h[DIM * DIM];
__device__ __nv_bfloat16 g_w1t_l[DIM * DIM];
__device__ __nv_bfloat16 g_w2t_h[DIM * DIM];
__device__ __nv_bfloat16 g_w2t_l[DIM * DIM];

// ---------------- mma.sync + ldmatrix wrappers ----------------
__device__ __forceinline__ void mma16816(float* c, const uint32_t* a, const uint32_t* b) {
    asm volatile(
        "mma.sync.aligned.m16n8k16.row.col.f32.bf16.bf16.f32 "
        "{%0,%1,%2,%3}, {%4,%5,%6,%7}, {%8,%9}, {%0,%1,%2,%3};"
        : "+f"(c[0]), "+f"(c[1]), "+f"(c[2]), "+f"(c[3])
        : "r"(a[0]), "r"(a[1]), "r"(a[2]), "r"(a[3]), "r"(b[0]), "r"(b[1]));
}
#define LDMX4(r0, r1, r2, r3, addr) \
    asm volatile("ldmatrix.sync.aligned.m8n8.x4.shared.b16 {%0,%1,%2,%3}, [%4];" \
        : "=r"(r0), "=r"(r1), "=r"(r2), "=r"(r3) : "r"(addr))

// ---------------- HMMA split GEMM (R8 config: 128x128 CTA, 8 warps of 32x64) --------
// PRE=0: A fp32 converted in-register; PRE=1: A pre-split bf16 hi/lo.
// MODE 0: C = AB ; MODE 1: C = res + relu(AB+bias) ; MODE 2: C = res + AB + bias
template <int MODE, int PRE>
__global__ void __launch_bounds__(256, 2)
mma_gemm_k(const void* __restrict__ Ap, const void* __restrict__ Ap2, int K, int Kpad,
           const __nv_bfloat16* __restrict__ Bh, const __nv_bfloat16* __restrict__ Bl,
           int M,
           const float* __restrict__ bias, const float* __restrict__ res,
           float* __restrict__ C) {
    __shared__ __align__(16) __nv_bfloat16 sAh[128 * MT_S];
    __shared__ __align__(16) __nv_bfloat16 sAl[128 * MT_S];
    __shared__ __align__(16) __nv_bfloat16 sBh[128 * MT_S];
    __shared__ __align__(16) __nv_bfloat16 sBl[128 * MT_S];
    int tid = threadIdx.x;
    int wid = tid >> 5, lane = tid & 31;
    int wm = wid & 3;
    int wn = wid >> 2;
    int row0 = blockIdx.y * 128;
    int col0 = blockIdx.x * 128;

    uint32_t sAh_b = (uint32_t)__cvta_generic_to_shared(sAh);
    uint32_t sAl_b = (uint32_t)__cvta_generic_to_shared(sAl);
    uint32_t sBh_b = (uint32_t)__cvta_generic_to_shared(sBh);
    uint32_t sBl_b = (uint32_t)__cvta_generic_to_shared(sBl);

    float acc[2][8][4];
    #pragma unroll
    for (int mt = 0; mt < 2; mt++)
        #pragma unroll
        for (int nt = 0; nt < 8; nt++)
            #pragma unroll
            for (int q = 0; q < 4; q++) acc[mt][nt][q] = 0.f;

    int lr = tid >> 1;
    int seg = (tid & 1) * 16;
    int gr = row0 + lr;
    bool arow_ok = gr < M;
    const float* Arow = (const float*)Ap + (size_t)(arow_ok ? gr : 0) * K;
    const __nv_bfloat16* AhRow = (const __nv_bfloat16*)Ap + (size_t)(arow_ok ? gr : 0) * Kpad;
    const __nv_bfloat16* AlRow = (const __nv_bfloat16*)Ap2 + (size_t)(arow_ok ? gr : 0) * Kpad;
    const __nv_bfloat16* BhRow = Bh + (size_t)(col0 + lr) * Kpad;
    const __nv_bfloat16* BlRow = Bl + (size_t)(col0 + lr) * Kpad;

    float aF[16];
    uint4 ah[2], al[2];
    uint4 bh[2], bl[2];

    auto loadChunk = [&](int k0) {
        if (PRE) {
            ah[0] = *(const uint4*)(AhRow + k0 + seg);
            ah[1] = *(const uint4*)(AhRow + k0 + seg + 8);
            al[0] = *(const uint4*)(AlRow + k0 + seg);
            al[1] = *(const uint4*)(AlRow + k0 + seg + 8);
        } else {
            #pragma unroll
            for (int j = 0; j < 4; j++) {
                int gk = k0 + seg + j * 4;
                float4 v = make_float4(0.f, 0.f, 0.f, 0.f);
                if (arow_ok && gk + 3 < K) v = *(const float4*)(Arow + gk);
                else if (arow_ok) {
                    float tmp[4] = {0.f, 0.f, 0.f, 0.f};
                    #pragma unroll
                    for (int u = 0; u < 4; u++) if (gk + u < K) tmp[u] = Arow[gk + u];
                    v = make_float4(tmp[0], tmp[1], tmp[2], tmp[3]);
                }
                aF[j * 4 + 0] = v.x; aF[j * 4 + 1] = v.y;
                aF[j * 4 + 2] = v.z; aF[j * 4 + 3] = v.w;
            }
        }
        bh[0] = *(const uint4*)(BhRow + k0 + seg);
        bh[1] = *(const uint4*)(BhRow + k0 + seg + 8);
        bl[0] = *(const uint4*)(BlRow + k0 + seg);
        bl[1] = *(const uint4*)(BlRow + k0 + seg + 8);
    };
    auto storeChunk = [&]() {
        if (PRE) {
            *(uint4*)&sAh[lr * MT_S + seg]     = ah[0];
            *(uint4*)&sAh[lr * MT_S + seg + 8] = ah[1];
            *(uint4*)&sAl[lr * MT_S + seg]     = al[0];
            *(uint4*)&sAl[lr * MT_S + seg + 8] = al[1];
        } else {
            __nv_bfloat16 h[16], l[16];
            #pragma unroll
            for (int j = 0; j < 16; j++) {
                h[j] = __float2bfloat16(aF[j]);
                l[j] = __float2bfloat16(aF[j] - __bfloat162float(h[j]));
            }
            *(uint4*)&sAh[lr * MT_S + seg]     = ((const uint4*)h)[0];
            *(uint4*)&sAh[lr * MT_S + seg + 8] = ((const uint4*)h)[1];
            *(uint4*)&sAl[lr * MT_S + seg]     = ((const uint4*)l)[0];
            *(uint4*)&sAl[lr * MT_S + seg + 8] = ((const uint4*)l)[1];
        }
        *(uint4*)&sBh[lr * MT_S + seg]     = bh[0];
        *(uint4*)&sBh[lr * MT_S + seg + 8] = bh[1];
        *(uint4*)&sBl[lr * MT_S + seg]     = bl[0];
        *(uint4*)&sBl[lr * MT_S + seg + 8] = bl[1];
    };

    int a_row = wm * 32 + (lane & 15);
    int a_colsel = (lane >> 4) * 8;
    int b_row = wn * 64 + ((lane >> 4) ? 8 : 0) + (lane & 7);
    int b_colsel = ((lane >> 3) & 1) * 8;

    int nch = Kpad / 32;
    loadChunk(0);
    for (int ci = 0; ci < nch; ci++) {
        storeChunk();
        __syncthreads();
        if (ci + 1 < nch) loadChunk((ci + 1) * 32);
        #pragma unroll
        for (int ks = 0; ks < 2; ks++) {
            uint32_t aH[2][4], aL[2][4];
            #pragma unroll
            for (int mt = 0; mt < 2; mt++) {
                uint32_t off = (uint32_t)(((a_row + mt * 16) * MT_S + ks * 16 + a_colsel) * 2);
                LDMX4(aH[mt][0], aH[mt][1], aH[mt][2], aH[mt][3], sAh_b + off);
                LDMX4(aL[mt][0], aL[mt][1], aL[mt][2], aL[mt][3], sAl_b + off);
            }
            #pragma unroll
            for (int p = 0; p < 4; p++) {
                uint32_t off = (uint32_t)(((b_row + p * 16) * MT_S + ks * 16 + b_colsel) * 2);
                uint32_t h0, h1, h2, h3, l0, l1, l2, l3;
                LDMX4(h0, h1, h2, h3, sBh_b + off);
                LDMX4(l0, l1, l2, l3, sBl_b + off);
                uint32_t bH0[2] = {h0, h1}, bH1[2] = {h2, h3};
                uint32_t bL0[2] = {l0, l1}, bL1[2] = {l2, l3};
                #pragma unroll
                for (int mt = 0; mt < 2; mt++) {
                    mma16816(acc[mt][2 * p],     aH[mt], bH0);
                    mma16816(acc[mt][2 * p],     aL[mt], bH0);
                    mma16816(acc[mt][2 * p],     aH[mt], bL0);
                    mma16816(acc[mt][2 * p + 1], aH[mt], bH1);
                    mma16816(acc[mt][2 * p + 1], aL[mt], bH1);
                    mma16816(acc[mt][2 * p + 1], aH[mt], bL1);
                }
            }
        }
        __syncthreads();
    }

    #pragma unroll
    for (int mt = 0; mt < 2; mt++) {
        #pragma unroll
        for (int half = 0; half < 2; half++) {
            int r = row0 + wm * 32 + mt * 16 + (lane >> 2) + half * 8;
            if (r >= M) continue;
            #pragma unroll
            for (int nt = 0; nt < 8; nt++) {
                int c = col0 + wn * 64 + nt * 8 + (lane & 3) * 2;
                float2 v;
                v.x = acc[mt][nt][half * 2 + 0];
                v.y = acc[mt][nt][half * 2 + 1];
                if (MODE >= 1) {
                    const float2 bb = *(const float2*)&bias[c];
                    v.x += bb.x; v.y += bb.y;
                    if (MODE == 1) { v.x = fmaxf(v.x, 0.f); v.y = fmaxf(v.y, 0.f); }
                    const float2 rr = *(const float2*)&res[(size_t)r * 256 + c];
                    v.x += rr.x; v.y += rr.y;
                }
                *(float2*)&C[(size_t)r * 256 + c] = v;
            }
        }
    }
}

// ---------------- weight transpose + hi/lo split ----------------
__global__ void tsplit_k(const float* __restrict__ src, int K, int Kpad,
                         __nv_bfloat16* __restrict__ hi, __nv_bfloat16* __restrict__ lo) {
    int idx = blockIdx.x * blockDim.x + threadIdx.x;
    if (idx >= 256 * Kpad) return;
    int k = idx % Kpad;
    int n = idx / Kpad;
    float v = (k < K) ? src[(size_t)k * 256 + n] : 0.f;
    __nv_bfloat16 h = __float2bfloat16(v);
    hi[idx] = h;
    lo[idx] = __float2bfloat16(v - __bfloat162float(h));
}

// ---------------- stacked SIMT pipeline kernels ----------------
__global__ void zero_int_k(int* p, int n) {
    int i = blockIdx.x * blockDim.x + threadIdx.x;
    if (i < n) p[i] = 0;
}
__global__ void att_k(const float* __restrict__ att_feats,
                      const float* __restrict__ W_enc,
                      const float* __restrict__ a_w, int natt) {
    int r = blockIdx.x;
    int d = threadIdx.x;
    __shared__ float sh[DIM];
    __shared__ float sred[8];
    sh[d] = att_feats[(size_t)r * DIM + d];
    __syncthreads();
    float acc = 0.f;
    #pragma unroll 8
    for (int k = 0; k < DIM; k++) acc += sh[k] * W_enc[(size_t)k * DIM + d];
    g_attW[(size_t)r * DIM + d] = acc;
    float v = sh[d] * a_w[DIM + d];
    for (int o = 16; o; o >>= 1) v += __shfl_xor_sync(0xffffffffu, v, o);
    if ((d & 31) == 0) sred[d >> 5] = v;
    __syncthreads();
    if (d == 0) {
        float s = 0.f;
        #pragma unroll
        for (int i = 0; i < 8; i++) s += sred[i];
        g_attdot[r] = s;
    }
}
__global__ void entdot_all_k(const float* __restrict__ ent0, const float* __restrict__ ent1,
                             const float* __restrict__ a_w, int n0, int ntot) {
    int node = (blockIdx.x * blockDim.x + threadIdx.x) >> 5;
    int lane = threadIdx.x & 31;
    if (node >= ntot) return;
    const float* row = (node < n0) ? ent0 + (size_t)node * DIM
                                   : ent1 + (size_t)(node - n0) * DIM;
    float s = 0.f;
    #pragma unroll
    for (int d = lane; d < DIM; d += 32) s += row[d] * a_w[d];
    for (int o = 16; o; o >>= 1) s += __shfl_xor_sync(0xffffffffu, s, o);
    if (lane == 0) g_entdot[node] = s;
}
__global__ void hist_tri_all_k(const int* __restrict__ t0, const int* __restrict__ t1,
                               int ne0, int netot, int n0) {
    int e = blockIdx.x * blockDim.x + threadIdx.x;
    if (e >= netot) return;
    int head = (e < ne0) ? t0[3 * e] : n0 + t1[3 * (e - ne0)];
    atomicAdd(&g_cnt[head], 1);
}
__global__ void scan_blk_k(int n) {
    __shared__ int wsum[32];
    int b = blockIdx.x;
    int i = b * 1024 + threadIdx.x;
    int lane = threadIdx.x & 31, wid = threadIdx.x >> 5;
    int v = (i < n) ? g_cnt[i] : 0;
    int x = v;
    #pragma unroll
    for (int o = 1; o < 32; o <<= 1) {
        int y = __shfl_up_sync(0xffffffffu, x, o);
        if (lane >= o) x += y;
    }
    if (lane == 31) wsum[wid] = x;
    __syncthreads();
    if (wid == 0) {
        int w = wsum[lane];
        int xs = w;
        #pragma unroll
        for (int o = 1; o < 32; o <<= 1) {
            int y = __shfl_up_sync(0xffffffffu, xs, o);
            if (lane >= o) xs += y;
        }
        wsum[lane] = xs - w;
    }
    __syncthreads();
    int excl = wsum[wid] + x - v;
    if (i < n) g_ptr[i] = excl;
    if (threadIdx.x == 1023) g_bsum[b] = excl + v;
}
__global__ void scan_mid_k(int nb, int n) {
    int lane = threadIdx.x;
    int carry = 0;
    for (int base = 0; base < nb; base += 32) {
        int i = base + lane;
        int v = (i < nb) ? g_bsum[i] : 0;
        int x = v;
        #pragma unroll
        for (int o = 1; o < 32; o <<= 1) {
            int y = __shfl_up_sync(0xffffffffu, x, o);
            if (lane >= o) x += y;
        }
        if (i < nb) g_boff[i] = carry + x - v;
        carry += __shfl_sync(0xffffffffu, x, 31);
    }
    if (lane == 0) g_ptr[n] = carry;
}
__global__ void scan_add_k(int n) {
    int i = blockIdx.x * blockDim.x + threadIdx.x;
    if (i < n) {
        int p = g_ptr[i] + g_boff[i >> 10];
        g_ptr[i] = p;
        g_fill[i] = p;
    }
}
__global__ void scatter_tri_all_k(const int* __restrict__ t0, const int* __restrict__ t1,
                                  int ne0, int netot, int n0) {
    int e = blockIdx.x * blockDim.x + threadIdx.x;
    if (e >= netot) return;
    int head = (e < ne0) ? t0[3 * e] : n0 + t1[3 * (e - ne0)];
    int pos = atomicAdd(&g_fill[head], 1);
    g_idx[pos] = e;
}
__global__ void edge_ptr_all_k(const int* __restrict__ r0, const int* __restrict__ r1,
                               int E0, int Etot, int n0, int ntot) {
    int e = blockIdx.x * blockDim.x + threadIdx.x;
    if (e >= Etot) return;
    int r = (e < E0) ? r0[e] : n0 + r1[e - E0];
    if (e == 0) {
        for (int v = 0; v <= r; v++) g_eptr[v] = 0;
    } else {
        int rp = (e - 1 < E0) ? r0[e - 1] : n0 + r1[e - 1 - E0];
        for (int v = rp + 1; v <= r; v++) g_eptr[v] = e;
    }
    if (e == Etot - 1) {
        for (int v = r + 1; v <= ntot; v++) g_eptr[v] = Etot;
    }
}
// attr score pass: compute p per CSR slot (no valW dependency)
__global__ void attr_score_all_k(const int* __restrict__ t0, const int* __restrict__ t1,
                                 int ne0, const float* __restrict__ ab_ptr, int n0) {
    int v = blockIdx.x;
    int t = threadIdx.x;
    int s = g_ptr[v], e = g_ptr[v + 1];
    int side = v >= n0;
    const int* tri = side ? t1 : t0;
    int tbase = side ? ne0 : 0;
    __shared__ float sred[2];
    __shared__ float s_inv;
    float ab = ab_ptr[0];
    float ed = g_entdot[v];
    float part = 0.f;
    for (int i = s + t; i < e; i += 64) {
        int tt = g_idx[i] - tbase;
        float sc = ed + g_attdot[tri[3 * tt + 2]] + ab;
        sc = sc > 0.f ? sc : 0.2f * sc;
        float ex = expf(sc);
        g_p[i] = ex;
        part += ex;
    }
    for (int o = 16; o; o >>= 1) part += __shfl_xor_sync(0xffffffffu, part, o);
    if ((t & 31) == 0) sred[t >> 5] = part;
    __syncthreads();
    if (t == 0) {
        float rs = sred[0] + sred[1];
        s_inv = (rs > 0.f) ? 1.f / rs : 0.f;
    }
    __syncthreads();
    float inv_rs = s_inv;
    for (int i = s + t; i < e; i += 64) g_p[i] *= inv_rs;
}
// attr apply pass: gather attW/valW with stored p, add ent, ELU
__global__ void attr_apply_all_k(const int* __restrict__ t0, const int* __restrict__ t1,
                                 int ne0,
                                 const float* __restrict__ ent0, const float* __restrict__ ent1,
                                 int n0) {
    int v = blockIdx.x;
    int t = threadIdx.x;
    int s = g_ptr[v], e = g_ptr[v + 1];
    int side = v >= n0;
    const int* tri = side ? t1 : t0;
    int tbase = side ? ne0 : 0;
    __shared__ float sh_p[64];
    __shared__ int sh_att[64];
    __shared__ int sh_val[64];
    float4 acc = make_float4(0.f, 0.f, 0.f, 0.f);
    for (int base = s; base < e; base += 64) {
        int cnt = min(64, e - base);
        if (t < cnt) {
            int tt = g_idx[base + t] - tbase;
            sh_att[t] = tri[3 * tt + 2];
            sh_val[t] = tri[3 * tt + 1];
            sh_p[t] = g_p[base + t];
        }
        __syncthreads();
        for (int j = 0; j < cnt; j++) {
            float p = sh_p[j];
            const float4 aw = *(const float4*)&g_attW[(size_t)sh_att[j] * DIM + t * 4];
            const float4 vw = *(const float4*)&g_valW[(size_t)sh_val[j] * DIM + t * 4];
            acc.x += p * (aw.x + vw.x);
            acc.y += p * (aw.y + vw.y);
            acc.z += p * (aw.z + vw.z);
            acc.w += p * (aw.w + vw.w);
        }
        __syncthreads();
    }
    const float* ef_row = side ? ent1 + (size_t)(v - n0) * DIM : ent0 + (size_t)v * DIM;
    const float4 ef = *(const float4*)&ef_row[t * 4];
    float4 x = make_float4(acc.x + ef.x, acc.y + ef.y, acc.z + ef.z, acc.w + ef.w);
    x.x = x.x > 0.f ? x.x : expm1f(x.x);
    x.y = x.y > 0.f ? x.y : expm1f(x.y);
    x.z = x.z > 0.f ? x.z : expm1f(x.z);
    x.w = x.w > 0.f ? x.w : expm1f(x.w);
    *(float4*)&g_F1[(size_t)v * DIM + t * 4] = x;
}
__global__ void gcn_agg_split_all_k(const float* __restrict__ feats,
                                    const int* __restrict__ c0, const int* __restrict__ c1,
                                    int E0, int n0,
                                    __nv_bfloat16* __restrict__ hi,
                                    __nv_bfloat16* __restrict__ lo) {
    int v = blockIdx.x;
    int t = threadIdx.x;
    int s = g_eptr[v], e = g_eptr[v + 1];
    __shared__ int sh_c[64];
    float4 acc = make_float4(0.f, 0.f, 0.f, 0.f);
    for (int base = s; base < e; base += 64) {
        int cnt = min(64, e - base);
        if (t < cnt) {
            int i = base + t;
            sh_c[t] = (i < E0) ? c0[i] : n0 + c1[i - E0];
        }
        __syncthreads();
        for (int j = 0; j < cnt; j++) {
            const float4 f = *(const float4*)&feats[(size_t)sh_c[j] * DIM + t * 4];
            acc.x += f.x; acc.y += f.y; acc.z += f.z; acc.w += f.w;
        }
        __syncthreads();
    }
    float inv = (e > s) ? 1.f / (float)(e - s) : 0.f;
    float vals[4] = {acc.x * inv, acc.y * inv, acc.z * inv, acc.w * inv};
    __nv_bfloat16 hv[4], lv[4];
    #pragma unroll
    for (int j = 0; j < 4; j++) {
        hv[j] = __float2bfloat16(vals[j]);
        lv[j] = __float2bfloat16(vals[j] - __bfloat162float(hv[j]));
    }
    *(uint2*)&hi[(size_t)v * DIM + t * 4] = *(uint2*)hv;
    *(uint2*)&lo[(size_t)v * DIM + t * 4] = *(uint2*)lv;
}
__global__ void l2norm_all_k(const float* __restrict__ in, float* __restrict__ out) {
    int v = blockIdx.x;
    int t = threadIdx.x;
    __shared__ float sred[2];
    __shared__ float s_inv;
    const float4 x = *(const float4*)&in[(size_t)v * DIM + t * 4];
    float sq = x.x * x.x + x.y * x.y + x.z * x.z + x.w * x.w;
    for (int o = 16; o; o >>= 1) sq += __shfl_xor_sync(0xffffffffu, sq, o);
    if ((t & 31) == 0) sred[t >> 5] = sq;
    __syncthreads();
    if (t == 0) {
        float nrm = sqrtf(sred[0] + sred[1]);
        s_inv = 1.f / fmaxf(nrm, 1e-12f);
    }
    __syncthreads();
    float inv = s_inv;
    float4 y = make_float4(x.x * inv, x.y * inv, x.z * inv, x.w * inv);
    *(float4*)&out[(size_t)v * DIM + t * 4] = y;
}
__global__ void gather_all_k(const int* __restrict__ s0, const int* __restrict__ s1,
                             int nseed, int n0,
                             const float* __restrict__ src, float* __restrict__ dst) {
    int i = blockIdx.x;
    int t = threadIdx.x;
    int node = (i < nseed) ? s0[i] : n0 + s1[i - nseed];
    *(float4*)&dst[(size_t)i * DIM + t * 4] =
        *(const float4*)&src[(size_t)node * DIM + t * 4];
}

// ---------------- host orchestration ----------------
static inline int ceildiv(int a, int b) { return (a + b - 1) / b; }

extern "C" void kernel_launch(void* const* d_in, const int* in_sizes, int n_in,
                              void* d_out, int out_size) {
    const int* seed_sr = (const int*)d_in[0];
    const int* seed_tg = (const int*)d_in[1];
    const int* tri_sr  = (const int*)d_in[2];
    const int* tri_tg  = (const int*)d_in[3];
    const int* rows_sr = (const int*)d_in[4];
    const int* cols_sr = (const int*)d_in[5];
    const int* rows_tg = (const int*)d_in[6];
    const int* cols_tg = (const int*)d_in[7];
    const float* att_feats = (const float*)d_in[8];
    const float* val_feats = (const float*)d_in[9];
    const float* ent_sr = (const float*)d_in[10];
    const float* ent_tg = (const float*)d_in[11];
    const float* a_w   = (const float*)d_in[12];
    const float* a_b   = (const float*)d_in[13];
    const float* W_enc = (const float*)d_in[14];
    const float* w1    = (const float*)d_in[15];
    const float* b1    = (const float*)d_in[16];
    const float* w2    = (const float*)d_in[17];
    const float* b2    = (const float*)d_in[18];
    (void)n_in; (void)out_size;

    const int nseed  = in_sizes[0];
    const int ne0    = in_sizes[2] / 3;
    const int ne1    = in_sizes[3] / 3;
    const int E0     = in_sizes[4];
    const int E1     = in_sizes[6];
    const int natt   = in_sizes[8] / DIM;
    const int nval   = in_sizes[9] / 300;
    const int n0     = in_sizes[10] / DIM;
    const int n1     = in_sizes[11] / DIM;
    const int ntot   = n0 + n1;
    const int netot  = ne0 + ne1;
    const int Etot   = E0 + E1;

    static cudaStream_t s_aux = nullptr;
    static cudaEvent_t ev_fork = nullptr, ev_join = nullptr;
    if (!s_aux) {
        cudaStreamCreateWithFlags(&s_aux, cudaStreamNonBlocking);
        cudaEventCreateWithFlags(&ev_fork, cudaEventDisableTiming);
        cudaEventCreateWithFlags(&ev_join, cudaEventDisableTiming);
    }

    float* valW;  cudaGetSymbolAddress((void**)&valW,  g_valW);
    float* F1;    cudaGetSymbolAddress((void**)&F1,    g_F1);
    float* F2;    cudaGetSymbolAddress((void**)&F2,    g_F2);
    int*   cntp;  cudaGetSymbolAddress((void**)&cntp,  g_cnt);
    __nv_bfloat16 *xaH, *xaL, *wetH, *wetL, *w1tH, *w1tL, *w2tH, *w2tL;
    cudaGetSymbolAddress((void**)&xaH, g_xa_h);
    cudaGetSymbolAddress((void**)&xaL, g_xa_l);
    cudaGetSymbolAddress((void**)&wetH, g_wet_h);
    cudaGetSymbolAddress((void**)&wetL, g_wet_l);
    cudaGetSymbolAddress((void**)&w1tH, g_w1t_h);
    cudaGetSymbolAddress((void**)&w1tL, g_w1t_l);
    cudaGetSymbolAddress((void**)&w2tH, g_w2t_h);
    cudaGetSymbolAddress((void**)&w2tL, g_w2t_l);

    float* out = (float*)d_out;
    float* out_seed = out;
    float* out_full = out + (size_t)2 * nseed * DIM;

    // valW GEMM M-split: 80% aux, 20% main (row-tile aligned)
    int ntiles = ceildiv(nval, 128);
    int tiles_aux = (ntiles * 4 + 4) / 5;
    int m_aux = tiles_aux * 128;
    if (m_aux > nval) { m_aux = nval; tiles_aux = ntiles; }
    int m_main = nval - m_aux;

    // ---- fork: aux runs 80% of valW GEMM ----
    tsplit_k<<<ceildiv(256 * KPAD_VAL, 256), 256>>>(
        W_enc + (size_t)DIM * DIM, 300, KPAD_VAL, wetH, wetL);
    cudaEventRecord(ev_fork, 0);
    cudaStreamWaitEvent(s_aux, ev_fork, 0);
    {
        dim3 grid(2, tiles_aux);
        mma_gemm_k<0, 0><<<grid, 256, 0, s_aux>>>(
            val_feats, nullptr, 300, KPAD_VAL, wetH, wetL, m_aux,
            nullptr, nullptr, valW);
    }
    cudaEventRecord(ev_join, s_aux);

    // ---- main stream: precompute + CSR ----
    att_k<<<natt, DIM>>>(att_feats, W_enc, a_w, natt);
    tsplit_k<<<ceildiv(256 * 256, 256), 256>>>(w1, 256, 256, w1tH, w1tL);
    tsplit_k<<<ceildiv(256 * 256, 256), 256>>>(w2, 256, 256, w2tH, w2tL);
    entdot_all_k<<<ceildiv(ntot * 32, 256), 256>>>(ent_sr, ent_tg, a_w, n0, ntot);
    zero_int_k<<<ceildiv(ntot, 256), 256>>>(cntp, ntot);
    hist_tri_all_k<<<ceildiv(netot, 256), 256>>>(tri_sr, tri_tg, ne0, netot, n0);
    int nb = ceildiv(ntot, 1024);
    scan_blk_k<<<nb, 1024>>>(ntot);
    scan_mid_k<<<1, 32>>>(nb, ntot);
    scan_add_k<<<ceildiv(ntot, 256), 256>>>(ntot);
    scatter_tri_all_k<<<ceildiv(netot, 256), 256>>>(tri_sr, tri_tg, ne0, netot, n0);
    edge_ptr_all_k<<<ceildiv(Etot, 256), 256>>>(rows_sr, rows_tg, E0, Etot, n0, ntot);

    // main's 20% share of valW GEMM
    if (m_main > 0) {
        dim3 grid(2, ceildiv(m_main, 128));
        mma_gemm_k<0, 0><<<grid, 256>>>(
            val_feats + (size_t)m_aux * 300, nullptr, 300, KPAD_VAL, wetH, wetL, m_main,
            nullptr, nullptr, valW + (size_t)m_aux * 256);
    }
    // score pass (no valW dependency) overlaps aux GEMM tail
    attr_score_all_k<<<ntot, 64>>>(tri_sr, tri_tg, ne0, a_b, n0);

    // ---- join: apply needs full valW ----
    cudaStreamWaitEvent(0, ev_join, 0);
    attr_apply_all_k<<<ntot, 64>>>(tri_sr, tri_tg, ne0, ent_sr, ent_tg, n0);

    // ---- stacked GCN layers ----
    dim3 ggrid(2, ceildiv(ntot, 128));
    gcn_agg_split_all_k<<<ntot, 64>>>(F1, cols_sr, cols_tg, E0, n0, xaH, xaL);
    mma_gemm_k<1, 1><<<ggrid, 256>>>(xaH, xaL, 256, 256, w1tH, w1tL, ntot, b1, F1, F2);
    gcn_agg_split_all_k<<<ntot, 64>>>(F2, cols_sr, cols_tg, E0, n0, xaH, xaL);
    mma_gemm_k<2, 1><<<ggrid, 256>>>(xaH, xaL, 256, 256, w2tH, w2tL, ntot, b2, F2, F1);

    // ---- output ----
    l2norm_all_k<<<ntot, 64>>>(F1, out_full);
    gather_all_k<<<2 * nseed, 64>>>(seed_sr, seed_tg, nseed, n0, out_full, out_seed);
}

// round 13
// speedup vs baseline: 1.2582x; 1.2582x over previous
#include <cuda_runtime.h>
#include <cuda_fp16.h>
#include <math.h>
#include <stdint.h>

#define DIM 256
#define NTOT 100000
#define ETRI 400000
#define NVALMAX 100000
#define NATTMAX 1001
#define KPAD_VAL 320
#define MT_S 40   // smem row stride in fp16 (80B): conflict-free for ldmatrix 8-row phases

// ---------------- scratch ----------------
__device__ float g_valW[NVALMAX * DIM];
__device__ float g_attW[NATTMAX * DIM];
__device__ float g_attdot[NATTMAX];
__device__ float g_entdot[NTOT];
__device__ int   g_cnt[NTOT];
__device__ int   g_ptr[NTOT + 1];
__device__ int   g_eptr[NTOT + 1];
__device__ int   g_fill[NTOT];
__device__ int   g_idx[ETRI];
__device__ int   g_bsum[128];
__device__ int   g_boff[128];
__device__ float g_F1[NTOT * DIM];
__device__ float g_F2[NTOT * DIM];
// fp16 hi/lo A operand (GCN agg output)
__device__ __half g_xa_h[NTOT * DIM];
__device__ __half g_xa_l[NTOT * DIM];
// fp16 B operands (weights, transposed; single term)
__device__ __half g_wet[DIM * KPAD_VAL];
__device__ __half g_w1t[DIM * DIM];
__device__ __half g_w2t[DIM * DIM];

// ---------------- mma.sync + ldmatrix wrappers ----------------
__device__ __forceinline__ void mma16816(float* c, const uint32_t* a, const uint32_t* b) {
    asm volatile(
        "mma.sync.aligned.m16n8k16.row.col.f32.f16.f16.f32 "
        "{%0,%1,%2,%3}, {%4,%5,%6,%7}, {%8,%9}, {%0,%1,%2,%3};"
        : "+f"(c[0]), "+f"(c[1]), "+f"(c[2]), "+f"(c[3])
        : "r"(a[0]), "r"(a[1]), "r"(a[2]), "r"(a[3]), "r"(b[0]), "r"(b[1]));
}
#define LDMX4(r0, r1, r2, r3, addr) \
    asm volatile("ldmatrix.sync.aligned.m8n8.x4.shared.b16 {%0,%1,%2,%3}, [%4];" \
        : "=r"(r0), "=r"(r1), "=r"(r2), "=r"(r3) : "r"(addr))

// ---------------- HMMA fp16 2-term GEMM: 128x128 CTA, 8 warps of 32x64 --------------
// A = Ah + Al (fp16 pair, exact to ~2^-22); B = Bh (fp16). D = AhBh + AlBh = A*Bh.
// PRE=0: A fp32 converted in-register; PRE=1: A pre-split fp16 hi/lo.
// MODE 0: C = AB ; MODE 1: C = res + relu(AB+bias) ; MODE 2: C = res + AB + bias
template <int MODE, int PRE>
__global__ void __launch_bounds__(256, 2)
mma_gemm_k(const void* __restrict__ Ap, const void* __restrict__ Ap2, int K, int Kpad,
           const __half* __restrict__ Bh, int M,
           const float* __restrict__ bias, const float* __restrict__ res,
           float* __restrict__ C) {
    __shared__ __align__(16) __half sAh[128 * MT_S];
    __shared__ __align__(16) __half sAl[128 * MT_S];
    __shared__ __align__(16) __half sBh[128 * MT_S];
    int tid = threadIdx.x;
    int wid = tid >> 5, lane = tid & 31;
    int wm = wid & 3;      // 4 warp-rows of 32
    int wn = wid >> 2;     // 2 warp-cols of 64
    int row0 = blockIdx.y * 128;
    int col0 = blockIdx.x * 128;

    uint32_t sAh_b = (uint32_t)__cvta_generic_to_shared(sAh);
    uint32_t sAl_b = (uint32_t)__cvta_generic_to_shared(sAl);
    uint32_t sBh_b = (uint32_t)__cvta_generic_to_shared(sBh);

    float acc[2][8][4];
    #pragma unroll
    for (int mt = 0; mt < 2; mt++)
        #pragma unroll
        for (int nt = 0; nt < 8; nt++)
            #pragma unroll
            for (int q = 0; q < 4; q++) acc[mt][nt][q] = 0.f;

    int lr = tid >> 1;            // 0..127
    int seg = (tid & 1) * 16;     // k offset 0 or 16
    int gr = row0 + lr;
    bool arow_ok = gr < M;
    const float* Arow = (const float*)Ap + (size_t)(arow_ok ? gr : 0) * K;
    const __half* AhRow = (const __half*)Ap + (size_t)(arow_ok ? gr : 0) * Kpad;
    const __half* AlRow = (const __half*)Ap2 + (size_t)(arow_ok ? gr : 0) * Kpad;
    const __half* BhRow = Bh + (size_t)(col0 + lr) * Kpad;

    float aF[16];
    uint4 ah[2], al[2];
    uint4 bh[2];

    auto loadChunk = [&](int k0) {
        if (PRE) {
            ah[0] = *(const uint4*)(AhRow + k0 + seg);
            ah[1] = *(const uint4*)(AhRow + k0 + seg + 8);
            al[0] = *(const uint4*)(AlRow + k0 + seg);
            al[1] = *(const uint4*)(AlRow + k0 + seg + 8);
        } else {
            #pragma unroll
            for (int j = 0; j < 4; j++) {
                int gk = k0 + seg + j * 4;
                float4 v = make_float4(0.f, 0.f, 0.f, 0.f);
                if (arow_ok && gk + 3 < K) v = *(const float4*)(Arow + gk);
                else if (arow_ok) {
                    float tmp[4] = {0.f, 0.f, 0.f, 0.f};
                    #pragma unroll
                    for (int u = 0; u < 4; u++) if (gk + u < K) tmp[u] = Arow[gk + u];
                    v = make_float4(tmp[0], tmp[1], tmp[2], tmp[3]);
                }
                aF[j * 4 + 0] = v.x; aF[j * 4 + 1] = v.y;
                aF[j * 4 + 2] = v.z; aF[j * 4 + 3] = v.w;
            }
        }
        bh[0] = *(const uint4*)(BhRow + k0 + seg);
        bh[1] = *(const uint4*)(BhRow + k0 + seg + 8);
    };
    auto storeChunk = [&]() {
        if (PRE) {
            *(uint4*)&sAh[lr * MT_S + seg]     = ah[0];
            *(uint4*)&sAh[lr * MT_S + seg + 8] = ah[1];
            *(uint4*)&sAl[lr * MT_S + seg]     = al[0];
            *(uint4*)&sAl[lr * MT_S + seg + 8] = al[1];
        } else {
            __half h[16], l[16];
            #pragma unroll
            for (int j = 0; j < 16; j++) {
                h[j] = __float2half(aF[j]);
                l[j] = __float2half(aF[j] - __half2float(h[j]));
            }
            *(uint4*)&sAh[lr * MT_S + seg]     = ((const uint4*)h)[0];
            *(uint4*)&sAh[lr * MT_S + seg + 8] = ((const uint4*)h)[1];
            *(uint4*)&sAl[lr * MT_S + seg]     = ((const uint4*)l)[0];
            *(uint4*)&sAl[lr * MT_S + seg + 8] = ((const uint4*)l)[1];
        }
        *(uint4*)&sBh[lr * MT_S + seg]     = bh[0];
        *(uint4*)&sBh[lr * MT_S + seg + 8] = bh[1];
    };

    int a_row = wm * 32 + (lane & 15);
    int a_colsel = (lane >> 4) * 8;
    int b_row = wn * 64 + ((lane >> 4) ? 8 : 0) + (lane & 7);
    int b_colsel = ((lane >> 3) & 1) * 8;

    int nch = Kpad / 32;
    loadChunk(0);
    for (int ci = 0; ci < nch; ci++) {
        storeChunk();
        __syncthreads();
        if (ci + 1 < nch) loadChunk((ci + 1) * 32);
        #pragma unroll
        for (int ks = 0; ks < 2; ks++) {
            uint32_t aH[2][4], aL[2][4];
            #pragma unroll
            for (int mt = 0; mt < 2; mt++) {
                uint32_t off = (uint32_t)(((a_row + mt * 16) * MT_S + ks * 16 + a_colsel) * 2);
                LDMX4(aH[mt][0], aH[mt][1], aH[mt][2], aH[mt][3], sAh_b + off);
                LDMX4(aL[mt][0], aL[mt][1], aL[mt][2], aL[mt][3], sAl_b + off);
            }
            #pragma unroll
            for (int p = 0; p < 4; p++) {
                uint32_t off = (uint32_t)(((b_row + p * 16) * MT_S + ks * 16 + b_colsel) * 2);
                uint32_t h0, h1, h2, h3;
                LDMX4(h0, h1, h2, h3, sBh_b + off);
                uint32_t bH0[2] = {h0, h1}, bH1[2] = {h2, h3};
                #pragma unroll
                for (int mt = 0; mt < 2; mt++) {
                    mma16816(acc[mt][2 * p],     aH[mt], bH0);
                    mma16816(acc[mt][2 * p],     aL[mt], bH0);
                    mma16816(acc[mt][2 * p + 1], aH[mt], bH1);
                    mma16816(acc[mt][2 * p + 1], aL[mt], bH1);
                }
            }
        }
        __syncthreads();
    }

    #pragma unroll
    for (int mt = 0; mt < 2; mt++) {
        #pragma unroll
        for (int half = 0; half < 2; half++) {
            int r = row0 + wm * 32 + mt * 16 + (lane >> 2) + half * 8;
            if (r >= M) continue;
            #pragma unroll
            for (int nt = 0; nt < 8; nt++) {
                int c = col0 + wn * 64 + nt * 8 + (lane & 3) * 2;
                float2 v;
                v.x = acc[mt][nt][half * 2 + 0];
                v.y = acc[mt][nt][half * 2 + 1];
                if (MODE >= 1) {
                    const float2 bb = *(const float2*)&bias[c];
                    v.x += bb.x; v.y += bb.y;
                    if (MODE == 1) { v.x = fmaxf(v.x, 0.f); v.y = fmaxf(v.y, 0.f); }
                    const float2 rr = *(const float2*)&res[(size_t)r * 256 + c];
                    v.x += rr.x; v.y += rr.y;
                }
                *(float2*)&C[(size_t)r * 256 + c] = v;
            }
        }
    }
}

// ---------------- weight transpose to fp16 (single term) ----------------
__global__ void tsplit_h_k(const float* __restrict__ src, int K, int Kpad,
                           __half* __restrict__ hi) {
    int idx = blockIdx.x * blockDim.x + threadIdx.x;
    if (idx >= 256 * Kpad) return;
    int k = idx % Kpad;
    int n = idx / Kpad;
    float v = (k < K) ? src[(size_t)k * 256 + n] : 0.f;
    hi[idx] = __float2half(v);
}

// ---------------- stacked SIMT pipeline kernels ----------------
__global__ void zero_int_k(int* p, int n) {
    int i = blockIdx.x * blockDim.x + threadIdx.x;
    if (i < n) p[i] = 0;
}
__global__ void att_k(const float* __restrict__ att_feats,
                      const float* __restrict__ W_enc,
                      const float* __restrict__ a_w, int natt) {
    int r = blockIdx.x;
    int d = threadIdx.x;
    __shared__ float sh[DIM];
    __shared__ float sred[8];
    sh[d] = att_feats[(size_t)r * DIM + d];
    __syncthreads();
    float acc = 0.f;
    #pragma unroll 8
    for (int k = 0; k < DIM; k++) acc += sh[k] * W_enc[(size_t)k * DIM + d];
    g_attW[(size_t)r * DIM + d] = acc;
    float v = sh[d] * a_w[DIM + d];
    for (int o = 16; o; o >>= 1) v += __shfl_xor_sync(0xffffffffu, v, o);
    if ((d & 31) == 0) sred[d >> 5] = v;
    __syncthreads();
    if (d == 0) {
        float s = 0.f;
        #pragma unroll
        for (int i = 0; i < 8; i++) s += sred[i];
        g_attdot[r] = s;
    }
}
__global__ void entdot_all_k(const float* __restrict__ ent0, const float* __restrict__ ent1,
                             const float* __restrict__ a_w, int n0, int ntot) {
    int node = (blockIdx.x * blockDim.x + threadIdx.x) >> 5;
    int lane = threadIdx.x & 31;
    if (node >= ntot) return;
    const float* row = (node < n0) ? ent0 + (size_t)node * DIM
                                   : ent1 + (size_t)(node - n0) * DIM;
    float s = 0.f;
    #pragma unroll
    for (int d = lane; d < DIM; d += 32) s += row[d] * a_w[d];
    for (int o = 16; o; o >>= 1) s += __shfl_xor_sync(0xffffffffu, s, o);
    if (lane == 0) g_entdot[node] = s;
}
__global__ void hist_tri_all_k(const int* __restrict__ t0, const int* __restrict__ t1,
                               int ne0, int netot, int n0) {
    int e = blockIdx.x * blockDim.x + threadIdx.x;
    if (e >= netot) return;
    int head = (e < ne0) ? t0[3 * e] : n0 + t1[3 * (e - ne0)];
    atomicAdd(&g_cnt[head], 1);
}
__global__ void scan_blk_k(int n) {
    __shared__ int wsum[32];
    int b = blockIdx.x;
    int i = b * 1024 + threadIdx.x;
    int lane = threadIdx.x & 31, wid = threadIdx.x >> 5;
    int v = (i < n) ? g_cnt[i] : 0;
    int x = v;
    #pragma unroll
    for (int o = 1; o < 32; o <<= 1) {
        int y = __shfl_up_sync(0xffffffffu, x, o);
        if (lane >= o) x += y;
    }
    if (lane == 31) wsum[wid] = x;
    __syncthreads();
    if (wid == 0) {
        int w = wsum[lane];
        int xs = w;
        #pragma unroll
        for (int o = 1; o < 32; o <<= 1) {
            int y = __shfl_up_sync(0xffffffffu, xs, o);
            if (lane >= o) xs += y;
        }
        wsum[lane] = xs - w;
    }
    __syncthreads();
    int excl = wsum[wid] + x - v;
    if (i < n) g_ptr[i] = excl;
    if (threadIdx.x == 1023) g_bsum[b] = excl + v;
}
__global__ void scan_mid_k(int nb, int n) {
    int lane = threadIdx.x;
    int carry = 0;
    for (int base = 0; base < nb; base += 32) {
        int i = base + lane;
        int v = (i < nb) ? g_bsum[i] : 0;
        int x = v;
        #pragma unroll
        for (int o = 1; o < 32; o <<= 1) {
            int y = __shfl_up_sync(0xffffffffu, x, o);
            if (lane >= o) x += y;
        }
        if (i < nb) g_boff[i] = carry + x - v;
        carry += __shfl_sync(0xffffffffu, x, 31);
    }
    if (lane == 0) g_ptr[n] = carry;
}
__global__ void scan_add_k(int n) {
    int i = blockIdx.x * blockDim.x + threadIdx.x;
    if (i < n) {
        int p = g_ptr[i] + g_boff[i >> 10];
        g_ptr[i] = p;
        g_fill[i] = p;
    }
}
__global__ void scatter_tri_all_k(const int* __restrict__ t0, const int* __restrict__ t1,
                                  int ne0, int netot, int n0) {
    int e = blockIdx.x * blockDim.x + threadIdx.x;
    if (e >= netot) return;
    int head = (e < ne0) ? t0[3 * e] : n0 + t1[3 * (e - ne0)];
    int pos = atomicAdd(&g_fill[head], 1);
    g_idx[pos] = e;
}
__global__ void edge_ptr_all_k(const int* __restrict__ r0, const int* __restrict__ r1,
                               int E0, int Etot, int n0, int ntot) {
    int e = blockIdx.x * blockDim.x + threadIdx.x;
    if (e >= Etot) return;
    int r = (e < E0) ? r0[e] : n0 + r1[e - E0];
    if (e == 0) {
        for (int v = 0; v <= r; v++) g_eptr[v] = 0;
    } else {
        int rp = (e - 1 < E0) ? r0[e - 1] : n0 + r1[e - 1 - E0];
        for (int v = rp + 1; v <= r; v++) g_eptr[v] = e;
    }
    if (e == Etot - 1) {
        for (int v = r + 1; v <= ntot; v++) g_eptr[v] = Etot;
    }
}
__global__ void attr_agg_all_k(const int* __restrict__ t0, const int* __restrict__ t1,
                               int ne0,
                               const float* __restrict__ ab_ptr,
                               const float* __restrict__ ent0, const float* __restrict__ ent1,
                               int n0) {
    int v = blockIdx.x;
    int t = threadIdx.x;
    int s = g_ptr[v], e = g_ptr[v + 1];
    int side = v >= n0;
    const int* tri = side ? t1 : t0;
    int tbase = side ? ne0 : 0;
    __shared__ float sred[2];
    __shared__ float s_inv;
    __shared__ float sh_p[64];
    __shared__ int sh_att[64];
    __shared__ int sh_val[64];
    float ab = ab_ptr[0];
    float ed = g_entdot[v];
    float part = 0.f;
    for (int i = s + t; i < e; i += 64) {
        int tt = g_idx[i] - tbase;
        float sc = ed + g_attdot[tri[3 * tt + 2]] + ab;
        sc = sc > 0.f ? sc : 0.2f * sc;
        part += expf(sc);
    }
    for (int o = 16; o; o >>= 1) part += __shfl_xor_sync(0xffffffffu, part, o);
    if ((t & 31) == 0) sred[t >> 5] = part;
    __syncthreads();
    if (t == 0) {
        float rs = sred[0] + sred[1];
        s_inv = (rs > 0.f) ? 1.f / rs : 0.f;
    }
    __syncthreads();
    float inv_rs = s_inv;
    float4 acc = make_float4(0.f, 0.f, 0.f, 0.f);
    for (int base = s; base < e; base += 64) {
        int cnt = min(64, e - base);
        if (t < cnt) {
            int tt = g_idx[base + t] - tbase;
            int att = tri[3 * tt + 2];
            int val = tri[3 * tt + 1];
            sh_att[t] = att;
            sh_val[t] = val;
            float sc = ed + g_attdot[att] + ab;
            sc = sc > 0.f ? sc : 0.2f * sc;
            sh_p[t] = expf(sc) * inv_rs;
        }
        __syncthreads();
        for (int j = 0; j < cnt; j++) {
            float p = sh_p[j];
            const float4 aw = *(const float4*)&g_attW[(size_t)sh_att[j] * DIM + t * 4];
            const float4 vw = *(const float4*)&g_valW[(size_t)sh_val[j] * DIM + t * 4];
            acc.x += p * (aw.x + vw.x);
            acc.y += p * (aw.y + vw.y);
            acc.z += p * (aw.z + vw.z);
            acc.w += p * (aw.w + vw.w);
        }
        __syncthreads();
    }
    const float* ef_row = side ? ent1 + (size_t)(v - n0) * DIM : ent0 + (size_t)v * DIM;
    const float4 ef = *(const float4*)&ef_row[t * 4];
    float4 x = make_float4(acc.x + ef.x, acc.y + ef.y, acc.z + ef.z, acc.w + ef.w);
    x.x = x.x > 0.f ? x.x : expm1f(x.x);
    x.y = x.y > 0.f ? x.y : expm1f(x.y);
    x.z = x.z > 0.f ? x.z : expm1f(x.z);
    x.w = x.w > 0.f ? x.w : expm1f(x.w);
    *(float4*)&g_F1[(size_t)v * DIM + t * 4] = x;
}
// GCN mean-agg over stacked graph; writes fp16 hi/lo split
__global__ void gcn_agg_split_all_k(const float* __restrict__ feats,
                                    const int* __restrict__ c0, const int* __restrict__ c1,
                                    int E0, int n0,
                                    __half* __restrict__ hi,
                                    __half* __restrict__ lo) {
    int v = blockIdx.x;
    int t = threadIdx.x;
    int s = g_eptr[v], e = g_eptr[v + 1];
    __shared__ int sh_c[64];
    float4 acc = make_float4(0.f, 0.f, 0.f, 0.f);
    for (int base = s; base < e; base += 64) {
        int cnt = min(64, e - base);
        if (t < cnt) {
            int i = base + t;
            sh_c[t] = (i < E0) ? c0[i] : n0 + c1[i - E0];
        }
        __syncthreads();
        for (int j = 0; j < cnt; j++) {
            const float4 f = *(const float4*)&feats[(size_t)sh_c[j] * DIM + t * 4];
            acc.x += f.x; acc.y += f.y; acc.z += f.z; acc.w += f.w;
        }
        __syncthreads();
    }
    float inv = (e > s) ? 1.f / (float)(e - s) : 0.f;
    float vals[4] = {acc.x * inv, acc.y * inv, acc.z * inv, acc.w * inv};
    __half hv[4], lv[4];
    #pragma unroll
    for (int j = 0; j < 4; j++) {
        hv[j] = __float2half(vals[j]);
        lv[j] = __float2half(vals[j] - __half2float(hv[j]));
    }
    *(uint2*)&hi[(size_t)v * DIM + t * 4] = *(uint2*)hv;
    *(uint2*)&lo[(size_t)v * DIM + t * 4] = *(uint2*)lv;
}
__global__ void l2norm_all_k(const float* __restrict__ in, float* __restrict__ out) {
    int v = blockIdx.x;
    int t = threadIdx.x;
    __shared__ float sred[2];
    __shared__ float s_inv;
    const float4 x = *(const float4*)&in[(size_t)v * DIM + t * 4];
    float sq = x.x * x.x + x.y * x.y + x.z * x.z + x.w * x.w;
    for (int o = 16; o; o >>= 1) sq += __shfl_xor_sync(0xffffffffu, sq, o);
    if ((t & 31) == 0) sred[t >> 5] = sq;
    __syncthreads();
    if (t == 0) {
        float nrm = sqrtf(sred[0] + sred[1]);
        s_inv = 1.f / fmaxf(nrm, 1e-12f);
    }
    __syncthreads();
    float inv = s_inv;
    float4 y = make_float4(x.x * inv, x.y * inv, x.z * inv, x.w * inv);
    *(float4*)&out[(size_t)v * DIM + t * 4] = y;
}
__global__ void gather_all_k(const int* __restrict__ s0, const int* __restrict__ s1,
                             int nseed, int n0,
                             const float* __restrict__ src, float* __restrict__ dst) {
    int i = blockIdx.x;
    int t = threadIdx.x;
    int node = (i < nseed) ? s0[i] : n0 + s1[i - nseed];
    *(float4*)&dst[(size_t)i * DIM + t * 4] =
        *(const float4*)&src[(size_t)node * DIM + t * 4];
}

// ---------------- host orchestration ----------------
static inline int ceildiv(int a, int b) { return (a + b - 1) / b; }

extern "C" void kernel_launch(void* const* d_in, const int* in_sizes, int n_in,
                              void* d_out, int out_size) {
    const int* seed_sr = (const int*)d_in[0];
    const int* seed_tg = (const int*)d_in[1];
    const int* tri_sr  = (const int*)d_in[2];
    const int* tri_tg  = (const int*)d_in[3];
    const int* rows_sr = (const int*)d_in[4];
    const int* cols_sr = (const int*)d_in[5];
    const int* rows_tg = (const int*)d_in[6];
    const int* cols_tg = (const int*)d_in[7];
    const float* att_feats = (const float*)d_in[8];
    const float* val_feats = (const float*)d_in[9];
    const float* ent_sr = (const float*)d_in[10];
    const float* ent_tg = (const float*)d_in[11];
    const float* a_w   = (const float*)d_in[12];
    const float* a_b   = (const float*)d_in[13];
    const float* W_enc = (const float*)d_in[14];
    const float* w1    = (const float*)d_in[15];
    const float* b1    = (const float*)d_in[16];
    const float* w2    = (const float*)d_in[17];
    const float* b2    = (const float*)d_in[18];
    (void)n_in; (void)out_size;

    const int nseed  = in_sizes[0];
    const int ne0    = in_sizes[2] / 3;
    const int ne1    = in_sizes[3] / 3;
    const int E0     = in_sizes[4];
    const int E1     = in_sizes[6];
    const int natt   = in_sizes[8] / DIM;
    const int nval   = in_sizes[9] / 300;
    const int n0     = in_sizes[10] / DIM;
    const int n1     = in_sizes[11] / DIM;
    const int ntot   = n0 + n1;
    const int netot  = ne0 + ne1;
    const int Etot   = E0 + E1;

    static cudaStream_t s_aux = nullptr;
    static cudaEvent_t ev_fork = nullptr, ev_join = nullptr;
    if (!s_aux) {
        cudaStreamCreateWithFlags(&s_aux, cudaStreamNonBlocking);
        cudaEventCreateWithFlags(&ev_fork, cudaEventDisableTiming);
        cudaEventCreateWithFlags(&ev_join, cudaEventDisableTiming);
    }

    float* valW;  cudaGetSymbolAddress((void**)&valW,  g_valW);
    float* F1;    cudaGetSymbolAddress((void**)&F1,    g_F1);
    float* F2;    cudaGetSymbolAddress((void**)&F2,    g_F2);
    int*   cntp;  cudaGetSymbolAddress((void**)&cntp,  g_cnt);
    __half *xaH, *xaL, *wet, *w1t, *w2t;
    cudaGetSymbolAddress((void**)&xaH, g_xa_h);
    cudaGetSymbolAddress((void**)&xaL, g_xa_l);
    cudaGetSymbolAddress((void**)&wet, g_wet);
    cudaGetSymbolAddress((void**)&w1t, g_w1t);
    cudaGetSymbolAddress((void**)&w2t, g_w2t);

    float* out = (float*)d_out;
    float* out_seed = out;
    float* out_full = out + (size_t)2 * nseed * DIM;

    // ---- precompute; valW GEMM forked to aux stream ----
    tsplit_h_k<<<ceildiv(256 * KPAD_VAL, 256), 256>>>(
        W_enc + (size_t)DIM * DIM, 300, KPAD_VAL, wet);
    cudaEventRecord(ev_fork, 0);
    cudaStreamWaitEvent(s_aux, ev_fork, 0);
    {
        dim3 grid(2, ceildiv(nval, 128));
        mma_gemm_k<0, 0><<<grid, 256, 0, s_aux>>>(
            val_feats, nullptr, 300, KPAD_VAL, wet, nval, nullptr, nullptr, valW);
    }
    cudaEventRecord(ev_join, s_aux);
    att_k<<<natt, DIM>>>(att_feats, W_enc, a_w, natt);
    tsplit_h_k<<<ceildiv(256 * 256, 256), 256>>>(w1, 256, 256, w1t);
    tsplit_h_k<<<ceildiv(256 * 256, 256), 256>>>(w2, 256, 256, w2t);
    entdot_all_k<<<ceildiv(ntot * 32, 256), 256>>>(ent_sr, ent_tg, a_w, n0, ntot);
    zero_int_k<<<ceildiv(ntot, 256), 256>>>(cntp, ntot);
    hist_tri_all_k<<<ceildiv(netot, 256), 256>>>(tri_sr, tri_tg, ne0, netot, n0);
    int nb = ceildiv(ntot, 1024);
    scan_blk_k<<<nb, 1024>>>(ntot);
    scan_mid_k<<<1, 32>>>(nb, ntot);
    scan_add_k<<<ceildiv(ntot, 256), 256>>>(ntot);
    scatter_tri_all_k<<<ceildiv(netot, 256), 256>>>(tri_sr, tri_tg, ne0, netot, n0);
    edge_ptr_all_k<<<ceildiv(Etot, 256), 256>>>(rows_sr, rows_tg, E0, Etot, n0, ntot);

    // ---- join: attr encoder needs valW ----
    cudaStreamWaitEvent(0, ev_join, 0);
    attr_agg_all_k<<<ntot, 64>>>(tri_sr, tri_tg, ne0, a_b, ent_sr, ent_tg, n0);

    // ---- stacked GCN layers ----
    dim3 ggrid(2, ceildiv(ntot, 128));
    gcn_agg_split_all_k<<<ntot, 64>>>(F1, cols_sr, cols_tg, E0, n0, xaH, xaL);
    mma_gemm_k<1, 1><<<ggrid, 256>>>(xaH, xaL, 256, 256, w1t, ntot, b1, F1, F2);
    gcn_agg_split_all_k<<<ntot, 64>>>(F2, cols_sr, cols_tg, E0, n0, xaH, xaL);
    mma_gemm_k<2, 1><<<ggrid, 256>>>(xaH, xaL, 256, 256, w2t, ntot, b2, F2, F1);

    // ---- output ----
    l2norm_all_k<<<ntot, 64>>>(F1, out_full);
    gather_all_k<<<2 * nseed, 64>>>(seed_sr, seed_tg, nseed, n0, out_full, out_seed);
}

// round 14
// speedup vs baseline: 1.2967x; 1.0306x over previous
#include <cuda_runtime.h>
#include <cuda_fp16.h>
#include <math.h>
#include <stdint.h>

#define DIM 256
#define NTOT 100000
#define ETRI 400000
#define NVALMAX 100000
#define NATTMAX 1001
#define KPAD_VAL 320
#define MT_S 40   // smem row stride in fp16 (80B): conflict-free for ldmatrix 8-row phases

// ---------------- scratch ----------------
__device__ __half g_valW[NVALMAX * DIM];    // fp16 table (written by valW GEMM)
__device__ __half g_attW[NATTMAX * DIM];    // fp16 table
__device__ float g_attdot[NATTMAX];
__device__ float g_entdot[NTOT];
__device__ int   g_cnt[NTOT];
__device__ int   g_ptr[NTOT + 1];
__device__ int   g_eptr[NTOT + 1];
__device__ int   g_fill[NTOT];
__device__ int   g_idx[ETRI];
__device__ int   g_bsum[128];
__device__ int   g_boff[128];
__device__ float g_F1[NTOT * DIM];
__device__ float g_F2[NTOT * DIM];
__device__ __half g_Fh[NTOT * DIM];         // fp16 copy of current agg input
__device__ __half g_xa_h[NTOT * DIM];
__device__ __half g_xa_l[NTOT * DIM];
__device__ __half g_wet[DIM * KPAD_VAL];
__device__ __half g_w1t[DIM * DIM];
__device__ __half g_w2t[DIM * DIM];

// ---------------- mma.sync + ldmatrix wrappers ----------------
__device__ __forceinline__ void mma16816(float* c, const uint32_t* a, const uint32_t* b) {
    asm volatile(
        "mma.sync.aligned.m16n8k16.row.col.f32.f16.f16.f32 "
        "{%0,%1,%2,%3}, {%4,%5,%6,%7}, {%8,%9}, {%0,%1,%2,%3};"
        : "+f"(c[0]), "+f"(c[1]), "+f"(c[2]), "+f"(c[3])
        : "r"(a[0]), "r"(a[1]), "r"(a[2]), "r"(a[3]), "r"(b[0]), "r"(b[1]));
}
#define LDMX4(r0, r1, r2, r3, addr) \
    asm volatile("ldmatrix.sync.aligned.m8n8.x4.shared.b16 {%0,%1,%2,%3}, [%4];" \
        : "=r"(r0), "=r"(r1), "=r"(r2), "=r"(r3) : "r"(addr))

// ---------------- HMMA fp16 2-term GEMM: 128x128 CTA, 8 warps of 32x64 --------------
// A = Ah + Al (fp16 pair); B = Bh (fp16). D = AhBh + AlBh (fp32 accum).
// PRE=0: A fp32 converted in-register; PRE=1: A pre-split fp16 hi/lo.
// MODE 0: Ch = AB (fp16 out) ; MODE 1: C = res + relu(AB+bias), Ch = fp16 copy ;
// MODE 2: C = res + AB + bias
template <int MODE, int PRE>
__global__ void __launch_bounds__(256, 2)
mma_gemm_k(const void* __restrict__ Ap, const void* __restrict__ Ap2, int K, int Kpad,
           const __half* __restrict__ Bh, int M,
           const float* __restrict__ bias, const float* __restrict__ res,
           float* __restrict__ C, __half* __restrict__ Ch) {
    __shared__ __align__(16) __half sAh[128 * MT_S];
    __shared__ __align__(16) __half sAl[128 * MT_S];
    __shared__ __align__(16) __half sBh[128 * MT_S];
    int tid = threadIdx.x;
    int wid = tid >> 5, lane = tid & 31;
    int wm = wid & 3;
    int wn = wid >> 2;
    int row0 = blockIdx.y * 128;
    int col0 = blockIdx.x * 128;

    uint32_t sAh_b = (uint32_t)__cvta_generic_to_shared(sAh);
    uint32_t sAl_b = (uint32_t)__cvta_generic_to_shared(sAl);
    uint32_t sBh_b = (uint32_t)__cvta_generic_to_shared(sBh);

    float acc[2][8][4];
    #pragma unroll
    for (int mt = 0; mt < 2; mt++)
        #pragma unroll
        for (int nt = 0; nt < 8; nt++)
            #pragma unroll
            for (int q = 0; q < 4; q++) acc[mt][nt][q] = 0.f;

    int lr = tid >> 1;
    int seg = (tid & 1) * 16;
    int gr = row0 + lr;
    bool arow_ok = gr < M;
    const float* Arow = (const float*)Ap + (size_t)(arow_ok ? gr : 0) * K;
    const __half* AhRow = (const __half*)Ap + (size_t)(arow_ok ? gr : 0) * Kpad;
    const __half* AlRow = (const __half*)Ap2 + (size_t)(arow_ok ? gr : 0) * Kpad;
    const __half* BhRow = Bh + (size_t)(col0 + lr) * Kpad;

    float aF[16];
    uint4 ah[2], al[2];
    uint4 bh[2];

    auto loadChunk = [&](int k0) {
        if (PRE) {
            ah[0] = *(const uint4*)(AhRow + k0 + seg);
            ah[1] = *(const uint4*)(AhRow + k0 + seg + 8);
            al[0] = *(const uint4*)(AlRow + k0 + seg);
            al[1] = *(const uint4*)(AlRow + k0 + seg + 8);
        } else {
            #pragma unroll
            for (int j = 0; j < 4; j++) {
                int gk = k0 + seg + j * 4;
                float4 v = make_float4(0.f, 0.f, 0.f, 0.f);
                if (arow_ok && gk + 3 < K) v = *(const float4*)(Arow + gk);
                else if (arow_ok) {
                    float tmp[4] = {0.f, 0.f, 0.f, 0.f};
                    #pragma unroll
                    for (int u = 0; u < 4; u++) if (gk + u < K) tmp[u] = Arow[gk + u];
                    v = make_float4(tmp[0], tmp[1], tmp[2], tmp[3]);
                }
                aF[j * 4 + 0] = v.x; aF[j * 4 + 1] = v.y;
                aF[j * 4 + 2] = v.z; aF[j * 4 + 3] = v.w;
            }
        }
        bh[0] = *(const uint4*)(BhRow + k0 + seg);
        bh[1] = *(const uint4*)(BhRow + k0 + seg + 8);
    };
    auto storeChunk = [&]() {
        if (PRE) {
            *(uint4*)&sAh[lr * MT_S + seg]     = ah[0];
            *(uint4*)&sAh[lr * MT_S + seg + 8] = ah[1];
            *(uint4*)&sAl[lr * MT_S + seg]     = al[0];
            *(uint4*)&sAl[lr * MT_S + seg + 8] = al[1];
        } else {
            __half h[16], l[16];
            #pragma unroll
            for (int j = 0; j < 16; j++) {
                h[j] = __float2half(aF[j]);
                l[j] = __float2half(aF[j] - __half2float(h[j]));
            }
            *(uint4*)&sAh[lr * MT_S + seg]     = ((const uint4*)h)[0];
            *(uint4*)&sAh[lr * MT_S + seg + 8] = ((const uint4*)h)[1];
            *(uint4*)&sAl[lr * MT_S + seg]     = ((const uint4*)l)[0];
            *(uint4*)&sAl[lr * MT_S + seg + 8] = ((const uint4*)l)[1];
        }
        *(uint4*)&sBh[lr * MT_S + seg]     = bh[0];
        *(uint4*)&sBh[lr * MT_S + seg + 8] = bh[1];
    };

    int a_row = wm * 32 + (lane & 15);
    int a_colsel = (lane >> 4) * 8;
    int b_row = wn * 64 + ((lane >> 4) ? 8 : 0) + (lane & 7);
    int b_colsel = ((lane >> 3) & 1) * 8;

    int nch = Kpad / 32;
    loadChunk(0);
    for (int ci = 0; ci < nch; ci++) {
        storeChunk();
        __syncthreads();
        if (ci + 1 < nch) loadChunk((ci + 1) * 32);
        #pragma unroll
        for (int ks = 0; ks < 2; ks++) {
            uint32_t aH[2][4], aL[2][4];
            #pragma unroll
            for (int mt = 0; mt < 2; mt++) {
                uint32_t off = (uint32_t)(((a_row + mt * 16) * MT_S + ks * 16 + a_colsel) * 2);
                LDMX4(aH[mt][0], aH[mt][1], aH[mt][2], aH[mt][3], sAh_b + off);
                LDMX4(aL[mt][0], aL[mt][1], aL[mt][2], aL[mt][3], sAl_b + off);
            }
            #pragma unroll
            for (int p = 0; p < 4; p++) {
                uint32_t off = (uint32_t)(((b_row + p * 16) * MT_S + ks * 16 + b_colsel) * 2);
                uint32_t h0, h1, h2, h3;
                LDMX4(h0, h1, h2, h3, sBh_b + off);
                uint32_t bH0[2] = {h0, h1}, bH1[2] = {h2, h3};
                #pragma unroll
                for (int mt = 0; mt < 2; mt++) {
                    mma16816(acc[mt][2 * p],     aH[mt], bH0);
                    mma16816(acc[mt][2 * p],     aL[mt], bH0);
                    mma16816(acc[mt][2 * p + 1], aH[mt], bH1);
                    mma16816(acc[mt][2 * p + 1], aL[mt], bH1);
                }
            }
        }
        __syncthreads();
    }

    #pragma unroll
    for (int mt = 0; mt < 2; mt++) {
        #pragma unroll
        for (int half = 0; half < 2; half++) {
            int r = row0 + wm * 32 + mt * 16 + (lane >> 2) + half * 8;
            if (r >= M) continue;
            #pragma unroll
            for (int nt = 0; nt < 8; nt++) {
                int c = col0 + wn * 64 + nt * 8 + (lane & 3) * 2;
                float2 v;
                v.x = acc[mt][nt][half * 2 + 0];
                v.y = acc[mt][nt][half * 2 + 1];
                if (MODE >= 1) {
                    const float2 bb = *(const float2*)&bias[c];
                    v.x += bb.x; v.y += bb.y;
                    if (MODE == 1) { v.x = fmaxf(v.x, 0.f); v.y = fmaxf(v.y, 0.f); }
                    const float2 rr = *(const float2*)&res[(size_t)r * 256 + c];
                    v.x += rr.x; v.y += rr.y;
                }
                if (MODE != 0) *(float2*)&C[(size_t)r * 256 + c] = v;
                if (MODE != 2) {
                    __half2 hv = __floats2half2_rn(v.x, v.y);
                    *(__half2*)&Ch[(size_t)r * 256 + c] = hv;
                }
            }
        }
    }
}

// ---------------- weight transpose to fp16 ----------------
__global__ void tsplit_h_k(const float* __restrict__ src, int K, int Kpad,
                           __half* __restrict__ hi) {
    int idx = blockIdx.x * blockDim.x + threadIdx.x;
    if (idx >= 256 * Kpad) return;
    int k = idx % Kpad;
    int n = idx / Kpad;
    float v = (k < K) ? src[(size_t)k * 256 + n] : 0.f;
    hi[idx] = __float2half(v);
}

// ---------------- stacked SIMT pipeline kernels ----------------
__global__ void zero_int_k(int* p, int n) {
    int i = blockIdx.x * blockDim.x + threadIdx.x;
    if (i < n) p[i] = 0;
}
__global__ void att_k(const float* __restrict__ att_feats,
                      const float* __restrict__ W_enc,
                      const float* __restrict__ a_w, int natt) {
    int r = blockIdx.x;
    int d = threadIdx.x;
    __shared__ float sh[DIM];
    __shared__ float sred[8];
    sh[d] = att_feats[(size_t)r * DIM + d];
    __syncthreads();
    float acc = 0.f;
    #pragma unroll 8
    for (int k = 0; k < DIM; k++) acc += sh[k] * W_enc[(size_t)k * DIM + d];
    g_attW[(size_t)r * DIM + d] = __float2half(acc);
    float v = sh[d] * a_w[DIM + d];
    for (int o = 16; o; o >>= 1) v += __shfl_xor_sync(0xffffffffu, v, o);
    if ((d & 31) == 0) sred[d >> 5] = v;
    __syncthreads();
    if (d == 0) {
        float s = 0.f;
        #pragma unroll
        for (int i = 0; i < 8; i++) s += sred[i];
        g_attdot[r] = s;
    }
}
__global__ void entdot_all_k(const float* __restrict__ ent0, const float* __restrict__ ent1,
                             const float* __restrict__ a_w, int n0, int ntot) {
    int node = (blockIdx.x * blockDim.x + threadIdx.x) >> 5;
    int lane = threadIdx.x & 31;
    if (node >= ntot) return;
    const float* row = (node < n0) ? ent0 + (size_t)node * DIM
                                   : ent1 + (size_t)(node - n0) * DIM;
    float s = 0.f;
    #pragma unroll
    for (int d = lane; d < DIM; d += 32) s += row[d] * a_w[d];
    for (int o = 16; o; o >>= 1) s += __shfl_xor_sync(0xffffffffu, s, o);
    if (lane == 0) g_entdot[node] = s;
}
__global__ void hist_tri_all_k(const int* __restrict__ t0, const int* __restrict__ t1,
                               int ne0, int netot, int n0) {
    int e = blockIdx.x * blockDim.x + threadIdx.x;
    if (e >= netot) return;
    int head = (e < ne0) ? t0[3 * e] : n0 + t1[3 * (e - ne0)];
    atomicAdd(&g_cnt[head], 1);
}
__global__ void scan_blk_k(int n) {
    __shared__ int wsum[32];
    int b = blockIdx.x;
    int i = b * 1024 + threadIdx.x;
    int lane = threadIdx.x & 31, wid = threadIdx.x >> 5;
    int v = (i < n) ? g_cnt[i] : 0;
    int x = v;
    #pragma unroll
    for (int o = 1; o < 32; o <<= 1) {
        int y = __shfl_up_sync(0xffffffffu, x, o);
        if (lane >= o) x += y;
    }
    if (lane == 31) wsum[wid] = x;
    __syncthreads();
    if (wid == 0) {
        int w = wsum[lane];
        int xs = w;
        #pragma unroll
        for (int o = 1; o < 32; o <<= 1) {
            int y = __shfl_up_sync(0xffffffffu, xs, o);
            if (lane >= o) xs += y;
        }
        wsum[lane] = xs - w;
    }
    __syncthreads();
    int excl = wsum[wid] + x - v;
    if (i < n) g_ptr[i] = excl;
    if (threadIdx.x == 1023) g_bsum[b] = excl + v;
}
__global__ void scan_mid_k(int nb, int n) {
    int lane = threadIdx.x;
    int carry = 0;
    for (int base = 0; base < nb; base += 32) {
        int i = base + lane;
        int v = (i < nb) ? g_bsum[i] : 0;
        int x = v;
        #pragma unroll
        for (int o = 1; o < 32; o <<= 1) {
            int y = __shfl_up_sync(0xffffffffu, x, o);
            if (lane >= o) x += y;
        }
        if (i < nb) g_boff[i] = carry + x - v;
        carry += __shfl_sync(0xffffffffu, x, 31);
    }
    if (lane == 0) g_ptr[n] = carry;
}
__global__ void scan_add_k(int n) {
    int i = blockIdx.x * blockDim.x + threadIdx.x;
    if (i < n) {
        int p = g_ptr[i] + g_boff[i >> 10];
        g_ptr[i] = p;
        g_fill[i] = p;
    }
}
__global__ void scatter_tri_all_k(const int* __restrict__ t0, const int* __restrict__ t1,
                                  int ne0, int netot, int n0) {
    int e = blockIdx.x * blockDim.x + threadIdx.x;
    if (e >= netot) return;
    int head = (e < ne0) ? t0[3 * e] : n0 + t1[3 * (e - ne0)];
    int pos = atomicAdd(&g_fill[head], 1);
    g_idx[pos] = e;
}
__global__ void edge_ptr_all_k(const int* __restrict__ r0, const int* __restrict__ r1,
                               int E0, int Etot, int n0, int ntot) {
    int e = blockIdx.x * blockDim.x + threadIdx.x;
    if (e >= Etot) return;
    int r = (e < E0) ? r0[e] : n0 + r1[e - E0];
    if (e == 0) {
        for (int v = 0; v <= r; v++) g_eptr[v] = 0;
    } else {
        int rp = (e - 1 < E0) ? r0[e - 1] : n0 + r1[e - 1 - E0];
        for (int v = rp + 1; v <= r; v++) g_eptr[v] = e;
    }
    if (e == Etot - 1) {
        for (int v = r + 1; v <= ntot; v++) g_eptr[v] = Etot;
    }
}
__device__ __forceinline__ float4 half4_to_float4(uint2 u) {
    __half2 a = *(__half2*)&u.x;
    __half2 b = *(__half2*)&u.y;
    float2 fa = __half22float2(a);
    float2 fb = __half22float2(b);
    return make_float4(fa.x, fa.y, fb.x, fb.y);
}
__global__ void attr_agg_all_k(const int* __restrict__ t0, const int* __restrict__ t1,
                               int ne0,
                               const float* __restrict__ ab_ptr,
                               const float* __restrict__ ent0, const float* __restrict__ ent1,
                               int n0) {
    int v = blockIdx.x;
    int t = threadIdx.x;
    int s = g_ptr[v], e = g_ptr[v + 1];
    int side = v >= n0;
    const int* tri = side ? t1 : t0;
    int tbase = side ? ne0 : 0;
    __shared__ float sred[2];
    __shared__ float s_inv;
    __shared__ float sh_p[64];
    __shared__ int sh_att[64];
    __shared__ int sh_val[64];
    float ab = ab_ptr[0];
    float ed = g_entdot[v];
    float part = 0.f;
    for (int i = s + t; i < e; i += 64) {
        int tt = g_idx[i] - tbase;
        float sc = ed + g_attdot[tri[3 * tt + 2]] + ab;
        sc = sc > 0.f ? sc : 0.2f * sc;
        part += expf(sc);
    }
    for (int o = 16; o; o >>= 1) part += __shfl_xor_sync(0xffffffffu, part, o);
    if ((t & 31) == 0) sred[t >> 5] = part;
    __syncthreads();
    if (t == 0) {
        float rs = sred[0] + sred[1];
        s_inv = (rs > 0.f) ? 1.f / rs : 0.f;
    }
    __syncthreads();
    float inv_rs = s_inv;
    float4 acc = make_float4(0.f, 0.f, 0.f, 0.f);
    for (int base = s; base < e; base += 64) {
        int cnt = min(64, e - base);
        if (t < cnt) {
            int tt = g_idx[base + t] - tbase;
            int att = tri[3 * tt + 2];
            int val = tri[3 * tt + 1];
            sh_att[t] = att;
            sh_val[t] = val;
            float sc = ed + g_attdot[att] + ab;
            sc = sc > 0.f ? sc : 0.2f * sc;
            sh_p[t] = expf(sc) * inv_rs;
        }
        __syncthreads();
        for (int j = 0; j < cnt; j++) {
            float p = sh_p[j];
            float4 aw = half4_to_float4(*(const uint2*)&g_attW[(size_t)sh_att[j] * DIM + t * 4]);
            float4 vw = half4_to_float4(*(const uint2*)&g_valW[(size_t)sh_val[j] * DIM + t * 4]);
            acc.x += p * (aw.x + vw.x);
            acc.y += p * (aw.y + vw.y);
            acc.z += p * (aw.z + vw.z);
            acc.w += p * (aw.w + vw.w);
        }
        __syncthreads();
    }
    const float* ef_row = side ? ent1 + (size_t)(v - n0) * DIM : ent0 + (size_t)v * DIM;
    const float4 ef = *(const float4*)&ef_row[t * 4];
    float4 x = make_float4(acc.x + ef.x, acc.y + ef.y, acc.z + ef.z, acc.w + ef.w);
    x.x = x.x > 0.f ? x.x : expm1f(x.x);
    x.y = x.y > 0.f ? x.y : expm1f(x.y);
    x.z = x.z > 0.f ? x.z : expm1f(x.z);
    x.w = x.w > 0.f ? x.w : expm1f(x.w);
    *(float4*)&g_F1[(size_t)v * DIM + t * 4] = x;
    __half h4[4] = {__float2half(x.x), __float2half(x.y),
                    __float2half(x.z), __float2half(x.w)};
    *(uint2*)&g_Fh[(size_t)v * DIM + t * 4] = *(uint2*)h4;
}
// GCN mean-agg over stacked graph, gathering the fp16 feature copy
__global__ void gcn_agg_split_all_k(const int* __restrict__ c0, const int* __restrict__ c1,
                                    int E0, int n0,
                                    __half* __restrict__ hi,
                                    __half* __restrict__ lo) {
    int v = blockIdx.x;
    int t = threadIdx.x;
    int s = g_eptr[v], e = g_eptr[v + 1];
    __shared__ int sh_c[64];
    float4 acc = make_float4(0.f, 0.f, 0.f, 0.f);
    for (int base = s; base < e; base += 64) {
        int cnt = min(64, e - base);
        if (t < cnt) {
            int i = base + t;
            sh_c[t] = (i < E0) ? c0[i] : n0 + c1[i - E0];
        }
        __syncthreads();
        for (int j = 0; j < cnt; j++) {
            float4 f = half4_to_float4(*(const uint2*)&g_Fh[(size_t)sh_c[j] * DIM + t * 4]);
            acc.x += f.x; acc.y += f.y; acc.z += f.z; acc.w += f.w;
        }
        __syncthreads();
    }
    float inv = (e > s) ? 1.f / (float)(e - s) : 0.f;
    float vals[4] = {acc.x * inv, acc.y * inv, acc.z * inv, acc.w * inv};
    __half hv[4], lv[4];
    #pragma unroll
    for (int j = 0; j < 4; j++) {
        hv[j] = __float2half(vals[j]);
        lv[j] = __float2half(vals[j] - __half2float(hv[j]));
    }
    *(uint2*)&hi[(size_t)v * DIM + t * 4] = *(uint2*)hv;
    *(uint2*)&lo[(size_t)v * DIM + t * 4] = *(uint2*)lv;
}
__global__ void l2norm_all_k(const float* __restrict__ in, float* __restrict__ out) {
    int v = blockIdx.x;
    int t = threadIdx.x;
    __shared__ float sred[2];
    __shared__ float s_inv;
    const float4 x = *(const float4*)&in[(size_t)v * DIM + t * 4];
    float sq = x.x * x.x + x.y * x.y + x.z * x.z + x.w * x.w;
    for (int o = 16; o; o >>= 1) sq += __shfl_xor_sync(0xffffffffu, sq, o);
    if ((t & 31) == 0) sred[t >> 5] = sq;
    __syncthreads();
    if (t == 0) {
        float nrm = sqrtf(sred[0] + sred[1]);
        s_inv = 1.f / fmaxf(nrm, 1e-12f);
    }
    __syncthreads();
    float inv = s_inv;
    float4 y = make_float4(x.x * inv, x.y * inv, x.z * inv, x.w * inv);
    *(float4*)&out[(size_t)v * DIM + t * 4] = y;
}
__global__ void gather_all_k(const int* __restrict__ s0, const int* __restrict__ s1,
                             int nseed, int n0,
                             const float* __restrict__ src, float* __restrict__ dst) {
    int i = blockIdx.x;
    int t = threadIdx.x;
    int node = (i < nseed) ? s0[i] : n0 + s1[i - nseed];
    *(float4*)&dst[(size_t)i * DIM + t * 4] =
        *(const float4*)&src[(size_t)node * DIM + t * 4];
}

// ---------------- host orchestration ----------------
static inline int ceildiv(int a, int b) { return (a + b - 1) / b; }

extern "C" void kernel_launch(void* const* d_in, const int* in_sizes, int n_in,
                              void* d_out, int out_size) {
    const int* seed_sr = (const int*)d_in[0];
    const int* seed_tg = (const int*)d_in[1];
    const int* tri_sr  = (const int*)d_in[2];
    const int* tri_tg  = (const int*)d_in[3];
    const int* rows_sr = (const int*)d_in[4];
    const int* cols_sr = (const int*)d_in[5];
    const int* rows_tg = (const int*)d_in[6];
    const int* cols_tg = (const int*)d_in[7];
    const float* att_feats = (const float*)d_in[8];
    const float* val_feats = (const float*)d_in[9];
    const float* ent_sr = (const float*)d_in[10];
    const float* ent_tg = (const float*)d_in[11];
    const float* a_w   = (const float*)d_in[12];
    const float* a_b   = (const float*)d_in[13];
    const float* W_enc = (const float*)d_in[14];
    const float* w1    = (const float*)d_in[15];
    const float* b1    = (const float*)d_in[16];
    const float* w2    = (const float*)d_in[17];
    const float* b2    = (const float*)d_in[18];
    (void)n_in; (void)out_size;

    const int nseed  = in_sizes[0];
    const int ne0    = in_sizes[2] / 3;
    const int ne1    = in_sizes[3] / 3;
    const int E0     = in_sizes[4];
    const int E1     = in_sizes[6];
    const int natt   = in_sizes[8] / DIM;
    const int nval   = in_sizes[9] / 300;
    const int n0     = in_sizes[10] / DIM;
    const int n1     = in_sizes[11] / DIM;
    const int ntot   = n0 + n1;
    const int netot  = ne0 + ne1;
    const int Etot   = E0 + E1;

    static cudaStream_t s_aux = nullptr;
    static cudaEvent_t ev_fork = nullptr, ev_join = nullptr;
    if (!s_aux) {
        cudaStreamCreateWithFlags(&s_aux, cudaStreamNonBlocking);
        cudaEventCreateWithFlags(&ev_fork, cudaEventDisableTiming);
        cudaEventCreateWithFlags(&ev_join, cudaEventDisableTiming);
    }

    __half* valW; cudaGetSymbolAddress((void**)&valW, g_valW);
    float* F1;    cudaGetSymbolAddress((void**)&F1,   g_F1);
    float* F2;    cudaGetSymbolAddress((void**)&F2,   g_F2);
    __half* Fh;   cudaGetSymbolAddress((void**)&Fh,   g_Fh);
    int*   cntp;  cudaGetSymbolAddress((void**)&cntp, g_cnt);
    __half *xaH, *xaL, *wet, *w1t, *w2t;
    cudaGetSymbolAddress((void**)&xaH, g_xa_h);
    cudaGetSymbolAddress((void**)&xaL, g_xa_l);
    cudaGetSymbolAddress((void**)&wet, g_wet);
    cudaGetSymbolAddress((void**)&w1t, g_w1t);
    cudaGetSymbolAddress((void**)&w2t, g_w2t);

    float* out = (float*)d_out;
    float* out_seed = out;
    float* out_full = out + (size_t)2 * nseed * DIM;

    // ---- precompute; valW GEMM (fp16 out) forked to aux stream ----
    tsplit_h_k<<<ceildiv(256 * KPAD_VAL, 256), 256>>>(
        W_enc + (size_t)DIM * DIM, 300, KPAD_VAL, wet);
    cudaEventRecord(ev_fork, 0);
    cudaStreamWaitEvent(s_aux, ev_fork, 0);
    {
        dim3 grid(2, ceildiv(nval, 128));
        mma_gemm_k<0, 0><<<grid, 256, 0, s_aux>>>(
            val_feats, nullptr, 300, KPAD_VAL, wet, nval, nullptr, nullptr, nullptr, valW);
    }
    cudaEventRecord(ev_join, s_aux);
    att_k<<<natt, DIM>>>(att_feats, W_enc, a_w, natt);
    tsplit_h_k<<<ceildiv(256 * 256, 256), 256>>>(w1, 256, 256, w1t);
    tsplit_h_k<<<ceildiv(256 * 256, 256), 256>>>(w2, 256, 256, w2t);
    entdot_all_k<<<ceildiv(ntot * 32, 256), 256>>>(ent_sr, ent_tg, a_w, n0, ntot);
    zero_int_k<<<ceildiv(ntot, 256), 256>>>(cntp, ntot);
    hist_tri_all_k<<<ceildiv(netot, 256), 256>>>(tri_sr, tri_tg, ne0, netot, n0);
    int nb = ceildiv(ntot, 1024);
    scan_blk_k<<<nb, 1024>>>(ntot);
    scan_mid_k<<<1, 32>>>(nb, ntot);
    scan_add_k<<<ceildiv(ntot, 256), 256>>>(ntot);
    scatter_tri_all_k<<<ceildiv(netot, 256), 256>>>(tri_sr, tri_tg, ne0, netot, n0);
    edge_ptr_all_k<<<ceildiv(Etot, 256), 256>>>(rows_sr, rows_tg, E0, Etot, n0, ntot);

    // ---- join: attr encoder needs valW ----
    cudaStreamWaitEvent(0, ev_join, 0);
    attr_agg_all_k<<<ntot, 64>>>(tri_sr, tri_tg, ne0, a_b, ent_sr, ent_tg, n0);

    // ---- stacked GCN layers ----
    dim3 ggrid(2, ceildiv(ntot, 128));
    // layer 1: agg(Fh=F1) -> F2 fp32 + Fh fp16 copy
    gcn_agg_split_all_k<<<ntot, 64>>>(cols_sr, cols_tg, E0, n0, xaH, xaL);
    mma_gemm_k<1, 1><<<ggrid, 256>>>(xaH, xaL, 256, 256, w1t, ntot, b1, F1, F2, Fh);
    // layer 2: agg(Fh=F2) -> F1 fp32 (final)
    gcn_agg_split_all_k<<<ntot, 64>>>(cols_sr, cols_tg, E0, n0, xaH, xaL);
    mma_gemm_k<2, 1><<<ggrid, 256>>>(xaH, xaL, 256, 256, w2t, ntot, b2, F2, F1, nullptr);

    // ---- output ----
    l2norm_all_k<<<ntot, 64>>>(F1, out_full);
    gather_all_k<<<2 * nseed, 64>>>(seed_sr, seed_tg, nseed, n0, out_full, out_seed);
}

// round 15
// speedup vs baseline: 1.3594x; 1.0483x over previous
#include <cuda_runtime.h>
#include <cuda_fp16.h>
#include <math.h>
#include <stdint.h>

#define DIM 256
#define NTOT 100000
#define ETRI 400000
#define NVALMAX 100000
#define NATTMAX 1001
#define KPAD_VAL 320
#define MT_S 40   // smem row stride in fp16 (80B): conflict-free for ldmatrix 8-row phases

// ---------------- scratch ----------------
__device__ __half g_valW[NVALMAX * DIM];
__device__ __half g_attW[NATTMAX * DIM];
__device__ float g_attdot[NATTMAX];
__device__ float g_entdot[NTOT];
__device__ int   g_cnt[NTOT];
__device__ int   g_ptr[NTOT + 1];
__device__ int   g_eptr[NTOT + 1];
__device__ int   g_fill[NTOT];
__device__ int   g_idx[ETRI];
__device__ int   g_bsum[128];
__device__ int   g_boff[128];
__device__ float g_F1[NTOT * DIM];
__device__ float g_F2[NTOT * DIM];
__device__ __half g_Fh[NTOT * DIM];      // fp16 copy of current agg input
__device__ __half g_xa_h[NTOT * DIM];    // fp16 A operand for GCN GEMMs
__device__ __half g_wet[DIM * KPAD_VAL];
__device__ __half g_w1t[DIM * DIM];
__device__ __half g_w2t[DIM * DIM];

// ---------------- mma.sync + ldmatrix wrappers ----------------
__device__ __forceinline__ void mma16816(float* c, const uint32_t* a, const uint32_t* b) {
    asm volatile(
        "mma.sync.aligned.m16n8k16.row.col.f32.f16.f16.f32 "
        "{%0,%1,%2,%3}, {%4,%5,%6,%7}, {%8,%9}, {%0,%1,%2,%3};"
        : "+f"(c[0]), "+f"(c[1]), "+f"(c[2]), "+f"(c[3])
        : "r"(a[0]), "r"(a[1]), "r"(a[2]), "r"(a[3]), "r"(b[0]), "r"(b[1]));
}
#define LDMX4(r0, r1, r2, r3, addr) \
    asm volatile("ldmatrix.sync.aligned.m8n8.x4.shared.b16 {%0,%1,%2,%3}, [%4];" \
        : "=r"(r0), "=r"(r1), "=r"(r2), "=r"(r3) : "r"(addr))

__device__ __forceinline__ float4 half4_to_float4(uint2 u) {
    __half2 a = *(__half2*)&u.x;
    __half2 b = *(__half2*)&u.y;
    float2 fa = __half22float2(a);
    float2 fb = __half22float2(b);
    return make_float4(fa.x, fa.y, fb.x, fb.y);
}

// ---------------- HMMA fp16 GEMM: 128x128 CTA, 8 warps of 32x64 --------------
// TERMS=2: A = Ah + Al (fp16 pair); TERMS=1: A = Ah only. B = Bh fp16. fp32 accum.
// PRE=0: A fp32 converted in-register (TERMS=2); PRE=1: A pre-split fp16.
// MODE 0: Ch = AB (fp16 out) ; MODE 1: C = res + relu(AB+bias), Ch = fp16 copy ;
// MODE 2: C = res + AB + bias
template <int MODE, int PRE, int TERMS>
__global__ void __launch_bounds__(256, 2)
mma_gemm_k(const void* __restrict__ Ap, const void* __restrict__ Ap2, int K, int Kpad,
           const __half* __restrict__ Bh, int M,
           const float* __restrict__ bias, const float* __restrict__ res,
           float* __restrict__ C, __half* __restrict__ Ch) {
    __shared__ __align__(16) __half sAh[128 * MT_S];
    __shared__ __align__(16) __half sAl[TERMS == 2 ? 128 * MT_S : 8];
    __shared__ __align__(16) __half sBh[128 * MT_S];
    int tid = threadIdx.x;
    int wid = tid >> 5, lane = tid & 31;
    int wm = wid & 3;
    int wn = wid >> 2;
    int row0 = blockIdx.y * 128;
    int col0 = blockIdx.x * 128;

    uint32_t sAh_b = (uint32_t)__cvta_generic_to_shared(sAh);
    uint32_t sAl_b = (uint32_t)__cvta_generic_to_shared(sAl);
    uint32_t sBh_b = (uint32_t)__cvta_generic_to_shared(sBh);

    float acc[2][8][4];
    #pragma unroll
    for (int mt = 0; mt < 2; mt++)
        #pragma unroll
        for (int nt = 0; nt < 8; nt++)
            #pragma unroll
            for (int q = 0; q < 4; q++) acc[mt][nt][q] = 0.f;

    int lr = tid >> 1;
    int seg = (tid & 1) * 16;
    int gr = row0 + lr;
    bool arow_ok = gr < M;
    const float* Arow = (const float*)Ap + (size_t)(arow_ok ? gr : 0) * K;
    const __half* AhRow = (const __half*)Ap + (size_t)(arow_ok ? gr : 0) * Kpad;
    const __half* AlRow = (const __half*)Ap2 + (size_t)(arow_ok ? gr : 0) * Kpad;
    const __half* BhRow = Bh + (size_t)(col0 + lr) * Kpad;

    float aF[16];
    uint4 ah[2], al[2];
    uint4 bh[2];

    auto loadChunk = [&](int k0) {
        if (PRE) {
            ah[0] = *(const uint4*)(AhRow + k0 + seg);
            ah[1] = *(const uint4*)(AhRow + k0 + seg + 8);
            if (TERMS == 2) {
                al[0] = *(const uint4*)(AlRow + k0 + seg);
                al[1] = *(const uint4*)(AlRow + k0 + seg + 8);
            }
        } else {
            #pragma unroll
            for (int j = 0; j < 4; j++) {
                int gk = k0 + seg + j * 4;
                float4 v = make_float4(0.f, 0.f, 0.f, 0.f);
                if (arow_ok && gk + 3 < K) v = *(const float4*)(Arow + gk);
                else if (arow_ok) {
                    float tmp[4] = {0.f, 0.f, 0.f, 0.f};
                    #pragma unroll
                    for (int u = 0; u < 4; u++) if (gk + u < K) tmp[u] = Arow[gk + u];
                    v = make_float4(tmp[0], tmp[1], tmp[2], tmp[3]);
                }
                aF[j * 4 + 0] = v.x; aF[j * 4 + 1] = v.y;
                aF[j * 4 + 2] = v.z; aF[j * 4 + 3] = v.w;
            }
        }
        bh[0] = *(const uint4*)(BhRow + k0 + seg);
        bh[1] = *(const uint4*)(BhRow + k0 + seg + 8);
    };
    auto storeChunk = [&]() {
        if (PRE) {
            *(uint4*)&sAh[lr * MT_S + seg]     = ah[0];
            *(uint4*)&sAh[lr * MT_S + seg + 8] = ah[1];
            if (TERMS == 2) {
                *(uint4*)&sAl[lr * MT_S + seg]     = al[0];
                *(uint4*)&sAl[lr * MT_S + seg + 8] = al[1];
            }
        } else {
            __half h[16], l[16];
            #pragma unroll
            for (int j = 0; j < 16; j++) {
                h[j] = __float2half(aF[j]);
                l[j] = __float2half(aF[j] - __half2float(h[j]));
            }
            *(uint4*)&sAh[lr * MT_S + seg]     = ((const uint4*)h)[0];
            *(uint4*)&sAh[lr * MT_S + seg + 8] = ((const uint4*)h)[1];
            *(uint4*)&sAl[lr * MT_S + seg]     = ((const uint4*)l)[0];
            *(uint4*)&sAl[lr * MT_S + seg + 8] = ((const uint4*)l)[1];
        }
        *(uint4*)&sBh[lr * MT_S + seg]     = bh[0];
        *(uint4*)&sBh[lr * MT_S + seg + 8] = bh[1];
    };

    int a_row = wm * 32 + (lane & 15);
    int a_colsel = (lane >> 4) * 8;
    int b_row = wn * 64 + ((lane >> 4) ? 8 : 0) + (lane & 7);
    int b_colsel = ((lane >> 3) & 1) * 8;

    int nch = Kpad / 32;
    loadChunk(0);
    for (int ci = 0; ci < nch; ci++) {
        storeChunk();
        __syncthreads();
        if (ci + 1 < nch) loadChunk((ci + 1) * 32);
        #pragma unroll
        for (int ks = 0; ks < 2; ks++) {
            uint32_t aH[2][4], aL[2][4];
            #pragma unroll
            for (int mt = 0; mt < 2; mt++) {
                uint32_t off = (uint32_t)(((a_row + mt * 16) * MT_S + ks * 16 + a_colsel) * 2);
                LDMX4(aH[mt][0], aH[mt][1], aH[mt][2], aH[mt][3], sAh_b + off);
                if (TERMS == 2)
                    LDMX4(aL[mt][0], aL[mt][1], aL[mt][2], aL[mt][3], sAl_b + off);
            }
            #pragma unroll
            for (int p = 0; p < 4; p++) {
                uint32_t off = (uint32_t)(((b_row + p * 16) * MT_S + ks * 16 + b_colsel) * 2);
                uint32_t h0, h1, h2, h3;
                LDMX4(h0, h1, h2, h3, sBh_b + off);
                uint32_t bH0[2] = {h0, h1}, bH1[2] = {h2, h3};
                #pragma unroll
                for (int mt = 0; mt < 2; mt++) {
                    mma16816(acc[mt][2 * p],     aH[mt], bH0);
                    mma16816(acc[mt][2 * p + 1], aH[mt], bH1);
                    if (TERMS == 2) {
                        mma16816(acc[mt][2 * p],     aL[mt], bH0);
                        mma16816(acc[mt][2 * p + 1], aL[mt], bH1);
                    }
                }
            }
        }
        __syncthreads();
    }

    #pragma unroll
    for (int mt = 0; mt < 2; mt++) {
        #pragma unroll
        for (int half = 0; half < 2; half++) {
            int r = row0 + wm * 32 + mt * 16 + (lane >> 2) + half * 8;
            if (r >= M) continue;
            #pragma unroll
            for (int nt = 0; nt < 8; nt++) {
                int c = col0 + wn * 64 + nt * 8 + (lane & 3) * 2;
                float2 v;
                v.x = acc[mt][nt][half * 2 + 0];
                v.y = acc[mt][nt][half * 2 + 1];
                if (MODE >= 1) {
                    const float2 bb = *(const float2*)&bias[c];
                    v.x += bb.x; v.y += bb.y;
                    if (MODE == 1) { v.x = fmaxf(v.x, 0.f); v.y = fmaxf(v.y, 0.f); }
                    const float2 rr = *(const float2*)&res[(size_t)r * 256 + c];
                    v.x += rr.x; v.y += rr.y;
                }
                if (MODE != 0) *(float2*)&C[(size_t)r * 256 + c] = v;
                if (MODE != 2) {
                    __half2 hv = __floats2half2_rn(v.x, v.y);
                    *(__half2*)&Ch[(size_t)r * 256 + c] = hv;
                }
            }
        }
    }
}

// ---------------- weight transpose to fp16 ----------------
__global__ void tsplit_h_k(const float* __restrict__ src, int K, int Kpad,
                           __half* __restrict__ hi) {
    int idx = blockIdx.x * blockDim.x + threadIdx.x;
    if (idx >= 256 * Kpad) return;
    int k = idx % Kpad;
    int n = idx / Kpad;
    float v = (k < K) ? src[(size_t)k * 256 + n] : 0.f;
    hi[idx] = __float2half(v);
}

// ---------------- stacked SIMT pipeline kernels ----------------
__global__ void zero_int_k(int* p, int n) {
    int i = blockIdx.x * blockDim.x + threadIdx.x;
    if (i < n) p[i] = 0;
}
__global__ void att_k(const float* __restrict__ att_feats,
                      const float* __restrict__ W_enc,
                      const float* __restrict__ a_w, int natt) {
    int r = blockIdx.x;
    int d = threadIdx.x;
    __shared__ float sh[DIM];
    __shared__ float sred[8];
    sh[d] = att_feats[(size_t)r * DIM + d];
    __syncthreads();
    float acc = 0.f;
    #pragma unroll 8
    for (int k = 0; k < DIM; k++) acc += sh[k] * W_enc[(size_t)k * DIM + d];
    g_attW[(size_t)r * DIM + d] = __float2half(acc);
    float v = sh[d] * a_w[DIM + d];
    for (int o = 16; o; o >>= 1) v += __shfl_xor_sync(0xffffffffu, v, o);
    if ((d & 31) == 0) sred[d >> 5] = v;
    __syncthreads();
    if (d == 0) {
        float s = 0.f;
        #pragma unroll
        for (int i = 0; i < 8; i++) s += sred[i];
        g_attdot[r] = s;
    }
}
__global__ void entdot_all_k(const float* __restrict__ ent0, const float* __restrict__ ent1,
                             const float* __restrict__ a_w, int n0, int ntot) {
    int node = (blockIdx.x * blockDim.x + threadIdx.x) >> 5;
    int lane = threadIdx.x & 31;
    if (node >= ntot) return;
    const float* row = (node < n0) ? ent0 + (size_t)node * DIM
                                   : ent1 + (size_t)(node - n0) * DIM;
    float s = 0.f;
    #pragma unroll
    for (int d = lane; d < DIM; d += 32) s += row[d] * a_w[d];
    for (int o = 16; o; o >>= 1) s += __shfl_xor_sync(0xffffffffu, s, o);
    if (lane == 0) g_entdot[node] = s;
}
__global__ void hist_tri_all_k(const int* __restrict__ t0, const int* __restrict__ t1,
                               int ne0, int netot, int n0) {
    int e = blockIdx.x * blockDim.x + threadIdx.x;
    if (e >= netot) return;
    int head = (e < ne0) ? t0[3 * e] : n0 + t1[3 * (e - ne0)];
    atomicAdd(&g_cnt[head], 1);
}
__global__ void scan_blk_k(int n) {
    __shared__ int wsum[32];
    int b = blockIdx.x;
    int i = b * 1024 + threadIdx.x;
    int lane = threadIdx.x & 31, wid = threadIdx.x >> 5;
    int v = (i < n) ? g_cnt[i] : 0;
    int x = v;
    #pragma unroll
    for (int o = 1; o < 32; o <<= 1) {
        int y = __shfl_up_sync(0xffffffffu, x, o);
        if (lane >= o) x += y;
    }
    if (lane == 31) wsum[wid] = x;
    __syncthreads();
    if (wid == 0) {
        int w = wsum[lane];
        int xs = w;
        #pragma unroll
        for (int o = 1; o < 32; o <<= 1) {
            int y = __shfl_up_sync(0xffffffffu, xs, o);
            if (lane >= o) xs += y;
        }
        wsum[lane] = xs - w;
    }
    __syncthreads();
    int excl = wsum[wid] + x - v;
    if (i < n) g_ptr[i] = excl;
    if (threadIdx.x == 1023) g_bsum[b] = excl + v;
}
__global__ void scan_mid_k(int nb, int n) {
    int lane = threadIdx.x;
    int carry = 0;
    for (int base = 0; base < nb; base += 32) {
        int i = base + lane;
        int v = (i < nb) ? g_bsum[i] : 0;
        int x = v;
        #pragma unroll
        for (int o = 1; o < 32; o <<= 1) {
            int y = __shfl_up_sync(0xffffffffu, x, o);
            if (lane >= o) x += y;
        }
        if (i < nb) g_boff[i] = carry + x - v;
        carry += __shfl_sync(0xffffffffu, x, 31);
    }
    if (lane == 0) g_ptr[n] = carry;
}
__global__ void scan_add_k(int n) {
    int i = blockIdx.x * blockDim.x + threadIdx.x;
    if (i < n) {
        int p = g_ptr[i] + g_boff[i >> 10];
        g_ptr[i] = p;
        g_fill[i] = p;
    }
}
__global__ void scatter_tri_all_k(const int* __restrict__ t0, const int* __restrict__ t1,
                                  int ne0, int netot, int n0) {
    int e = blockIdx.x * blockDim.x + threadIdx.x;
    if (e >= netot) return;
    int head = (e < ne0) ? t0[3 * e] : n0 + t1[3 * (e - ne0)];
    int pos = atomicAdd(&g_fill[head], 1);
    g_idx[pos] = e;
}
__global__ void edge_ptr_all_k(const int* __restrict__ r0, const int* __restrict__ r1,
                               int E0, int Etot, int n0, int ntot) {
    int e = blockIdx.x * blockDim.x + threadIdx.x;
    if (e >= Etot) return;
    int r = (e < E0) ? r0[e] : n0 + r1[e - E0];
    if (e == 0) {
        for (int v = 0; v <= r; v++) g_eptr[v] = 0;
    } else {
        int rp = (e - 1 < E0) ? r0[e - 1] : n0 + r1[e - 1 - E0];
        for (int v = rp + 1; v <= r; v++) g_eptr[v] = e;
    }
    if (e == Etot - 1) {
        for (int v = r + 1; v <= ntot; v++) g_eptr[v] = Etot;
    }
}
// attributed encoder: pass1 softmax denom; pass2 split-table gather (uint4 rows)
__global__ void attr_agg_all_k(const int* __restrict__ t0, const int* __restrict__ t1,
                               int ne0,
                               const float* __restrict__ ab_ptr,
                               const float* __restrict__ ent0, const float* __restrict__ ent1,
                               int n0) {
    int v = blockIdx.x;
    int t = threadIdx.x;          // 0..63
    int half_id = t >> 5;
    int ld = (t & 31) * 8;        // dim base (8 dims per lane)
    int s = g_ptr[v], e = g_ptr[v + 1];
    int side = v >= n0;
    const int* tri = side ? t1 : t0;
    int tbase = side ? ne0 : 0;
    __shared__ float sred[2];
    __shared__ float s_inv;
    __shared__ float sh_p[64];
    __shared__ int sh_att[64];
    __shared__ int sh_val[64];
    __shared__ float sh_acc[32][8];
    float ab = ab_ptr[0];
    float ed = g_entdot[v];
    float part = 0.f;
    for (int i = s + t; i < e; i += 64) {
        int tt = g_idx[i] - tbase;
        float sc = ed + g_attdot[tri[3 * tt + 2]] + ab;
        sc = sc > 0.f ? sc : 0.2f * sc;
        part += expf(sc);
    }
    for (int o = 16; o; o >>= 1) part += __shfl_xor_sync(0xffffffffu, part, o);
    if ((t & 31) == 0) sred[t >> 5] = part;
    __syncthreads();
    if (t == 0) {
        float rs = sred[0] + sred[1];
        s_inv = (rs > 0.f) ? 1.f / rs : 0.f;
    }
    __syncthreads();
    float inv_rs = s_inv;
    float acc[8] = {0.f, 0.f, 0.f, 0.f, 0.f, 0.f, 0.f, 0.f};
    const __half* table = half_id ? g_valW : g_attW;
    for (int base = s; base < e; base += 64) {
        int cnt = min(64, e - base);
        if (t < cnt) {
            int tt = g_idx[base + t] - tbase;
            sh_att[t] = tri[3 * tt + 2];
            sh_val[t] = tri[3 * tt + 1];
            float sc = ed + g_attdot[sh_att[t]] + ab;
            sc = sc > 0.f ? sc : 0.2f * sc;
            sh_p[t] = expf(sc) * inv_rs;
        }
        __syncthreads();
        for (int j = 0; j < cnt; j++) {
            int row = half_id ? sh_val[j] : sh_att[j];
            float p = sh_p[j];
            uint4 u = *(const uint4*)&table[(size_t)row * DIM + ld];
            const __half2* hp = (const __half2*)&u;
            #pragma unroll
            for (int q = 0; q < 4; q++) {
                float2 f = __half22float2(hp[q]);
                acc[2 * q]     += p * f.x;
                acc[2 * q + 1] += p * f.y;
            }
        }
        __syncthreads();
    }
    if (half_id == 1) {
        #pragma unroll
        for (int q = 0; q < 8; q++) sh_acc[t & 31][q] = acc[q];
    }
    __syncthreads();
    if (half_id == 0) {
        const float* ef_row = side ? ent1 + (size_t)(v - n0) * DIM : ent0 + (size_t)v * DIM;
        float4 e0 = *(const float4*)&ef_row[ld];
        float4 e1 = *(const float4*)&ef_row[ld + 4];
        float ef[8] = {e0.x, e0.y, e0.z, e0.w, e1.x, e1.y, e1.z, e1.w};
        float outv[8];
        __half h8[8];
        #pragma unroll
        for (int q = 0; q < 8; q++) {
            float x = acc[q] + sh_acc[t][q] + ef[q];
            x = x > 0.f ? x : expm1f(x);
            outv[q] = x;
            h8[q] = __float2half(x);
        }
        *(float4*)&g_F1[(size_t)v * DIM + ld]     = make_float4(outv[0], outv[1], outv[2], outv[3]);
        *(float4*)&g_F1[(size_t)v * DIM + ld + 4] = make_float4(outv[4], outv[5], outv[6], outv[7]);
        *(uint4*)&g_Fh[(size_t)v * DIM + ld] = *(uint4*)h8;
    }
}
// GCN mean-agg: warp-halves take alternating neighbors; uint4 fp16 row loads;
// writes single-term fp16 A operand
__global__ void gcn_agg_h_k(const int* __restrict__ c0, const int* __restrict__ c1,
                            int E0, int n0, __half* __restrict__ outh) {
    int v = blockIdx.x;
    int t = threadIdx.x;          // 0..63
    int half_id = t >> 5;
    int ld = (t & 31) * 8;
    int s = g_eptr[v], e = g_eptr[v + 1];
    __shared__ int sh_c[64];
    __shared__ float sh_acc[32][8];
    float acc[8] = {0.f, 0.f, 0.f, 0.f, 0.f, 0.f, 0.f, 0.f};
    for (int base = s; base < e; base += 64) {
        int cnt = min(64, e - base);
        if (t < cnt) {
            int i = base + t;
            sh_c[t] = (i < E0) ? c0[i] : n0 + c1[i - E0];
        }
        __syncthreads();
        for (int j = half_id; j < cnt; j += 2) {
            uint4 u = *(const uint4*)&g_Fh[(size_t)sh_c[j] * DIM + ld];
            const __half2* hp = (const __half2*)&u;
            #pragma unroll
            for (int q = 0; q < 4; q++) {
                float2 f = __half22float2(hp[q]);
                acc[2 * q]     += f.x;
                acc[2 * q + 1] += f.y;
            }
        }
        __syncthreads();
    }
    if (half_id == 1) {
        #pragma unroll
        for (int q = 0; q < 8; q++) sh_acc[t & 31][q] = acc[q];
    }
    __syncthreads();
    if (half_id == 0) {
        float inv = (e > s) ? 1.f / (float)(e - s) : 0.f;
        __half h8[8];
        #pragma unroll
        for (int q = 0; q < 8; q++)
            h8[q] = __float2half((acc[q] + sh_acc[t][q]) * inv);
        *(uint4*)&outh[(size_t)v * DIM + ld] = *(uint4*)h8;
    }
}
__global__ void l2norm_all_k(const float* __restrict__ in, float* __restrict__ out) {
    int v = blockIdx.x;
    int t = threadIdx.x;
    __shared__ float sred[2];
    __shared__ float s_inv;
    const float4 x = *(const float4*)&in[(size_t)v * DIM + t * 4];
    float sq = x.x * x.x + x.y * x.y + x.z * x.z + x.w * x.w;
    for (int o = 16; o; o >>= 1) sq += __shfl_xor_sync(0xffffffffu, sq, o);
    if ((t & 31) == 0) sred[t >> 5] = sq;
    __syncthreads();
    if (t == 0) {
        float nrm = sqrtf(sred[0] + sred[1]);
        s_inv = 1.f / fmaxf(nrm, 1e-12f);
    }
    __syncthreads();
    float inv = s_inv;
    float4 y = make_float4(x.x * inv, x.y * inv, x.z * inv, x.w * inv);
    *(float4*)&out[(size_t)v * DIM + t * 4] = y;
}
__global__ void gather_all_k(const int* __restrict__ s0, const int* __restrict__ s1,
                             int nseed, int n0,
                             const float* __restrict__ src, float* __restrict__ dst) {
    int i = blockIdx.x;
    int t = threadIdx.x;
    int node = (i < nseed) ? s0[i] : n0 + s1[i - nseed];
    *(float4*)&dst[(size_t)i * DIM + t * 4] =
        *(const float4*)&src[(size_t)node * DIM + t * 4];
}

// ---------------- host orchestration ----------------
static inline int ceildiv(int a, int b) { return (a + b - 1) / b; }

extern "C" void kernel_launch(void* const* d_in, const int* in_sizes, int n_in,
                              void* d_out, int out_size) {
    const int* seed_sr = (const int*)d_in[0];
    const int* seed_tg = (const int*)d_in[1];
    const int* tri_sr  = (const int*)d_in[2];
    const int* tri_tg  = (const int*)d_in[3];
    const int* rows_sr = (const int*)d_in[4];
    const int* cols_sr = (const int*)d_in[5];
    const int* rows_tg = (const int*)d_in[6];
    const int* cols_tg = (const int*)d_in[7];
    const float* att_feats = (const float*)d_in[8];
    const float* val_feats = (const float*)d_in[9];
    const float* ent_sr = (const float*)d_in[10];
    const float* ent_tg = (const float*)d_in[11];
    const float* a_w   = (const float*)d_in[12];
    const float* a_b   = (const float*)d_in[13];
    const float* W_enc = (const float*)d_in[14];
    const float* w1    = (const float*)d_in[15];
    const float* b1    = (const float*)d_in[16];
    const float* w2    = (const float*)d_in[17];
    const float* b2    = (const float*)d_in[18];
    (void)n_in; (void)out_size;

    const int nseed  = in_sizes[0];
    const int ne0    = in_sizes[2] / 3;
    const int ne1    = in_sizes[3] / 3;
    const int E0     = in_sizes[4];
    const int E1     = in_sizes[6];
    const int natt   = in_sizes[8] / DIM;
    const int nval   = in_sizes[9] / 300;
    const int n0     = in_sizes[10] / DIM;
    const int n1     = in_sizes[11] / DIM;
    const int ntot   = n0 + n1;
    const int netot  = ne0 + ne1;
    const int Etot   = E0 + E1;

    static cudaStream_t s_aux = nullptr;
    static cudaEvent_t ev_fork = nullptr, ev_join = nullptr;
    if (!s_aux) {
        cudaStreamCreateWithFlags(&s_aux, cudaStreamNonBlocking);
        cudaEventCreateWithFlags(&ev_fork, cudaEventDisableTiming);
        cudaEventCreateWithFlags(&ev_join, cudaEventDisableTiming);
    }

    __half* valW; cudaGetSymbolAddress((void**)&valW, g_valW);
    float* F1;    cudaGetSymbolAddress((void**)&F1,   g_F1);
    float* F2;    cudaGetSymbolAddress((void**)&F2,   g_F2);
    __half* Fh;   cudaGetSymbolAddress((void**)&Fh,   g_Fh);
    int*   cntp;  cudaGetSymbolAddress((void**)&cntp, g_cnt);
    __half *xaH, *wet, *w1t, *w2t;
    cudaGetSymbolAddress((void**)&xaH, g_xa_h);
    cudaGetSymbolAddress((void**)&wet, g_wet);
    cudaGetSymbolAddress((void**)&w1t, g_w1t);
    cudaGetSymbolAddress((void**)&w2t, g_w2t);

    float* out = (float*)d_out;
    float* out_seed = out;
    float* out_full = out + (size_t)2 * nseed * DIM;

    // ---- precompute; valW GEMM (2-term A, fp16 out) forked to aux stream ----
    tsplit_h_k<<<ceildiv(256 * KPAD_VAL, 256), 256>>>(
        W_enc + (size_t)DIM * DIM, 300, KPAD_VAL, wet);
    cudaEventRecord(ev_fork, 0);
    cudaStreamWaitEvent(s_aux, ev_fork, 0);
    {
        dim3 grid(2, ceildiv(nval, 128));
        mma_gemm_k<0, 0, 2><<<grid, 256, 0, s_aux>>>(
            val_feats, nullptr, 300, KPAD_VAL, wet, nval, nullptr, nullptr, nullptr, valW);
    }
    cudaEventRecord(ev_join, s_aux);
    att_k<<<natt, DIM>>>(att_feats, W_enc, a_w, natt);
    tsplit_h_k<<<ceildiv(256 * 256, 256), 256>>>(w1, 256, 256, w1t);
    tsplit_h_k<<<ceildiv(256 * 256, 256), 256>>>(w2, 256, 256, w2t);
    entdot_all_k<<<ceildiv(ntot * 32, 256), 256>>>(ent_sr, ent_tg, a_w, n0, ntot);
    zero_int_k<<<ceildiv(ntot, 256), 256>>>(cntp, ntot);
    hist_tri_all_k<<<ceildiv(netot, 256), 256>>>(tri_sr, tri_tg, ne0, netot, n0);
    int nb = ceildiv(ntot, 1024);
    scan_blk_k<<<nb, 1024>>>(ntot);
    scan_mid_k<<<1, 32>>>(nb, ntot);
    scan_add_k<<<ceildiv(ntot, 256), 256>>>(ntot);
    scatter_tri_all_k<<<ceildiv(netot, 256), 256>>>(tri_sr, tri_tg, ne0, netot, n0);
    edge_ptr_all_k<<<ceildiv(Etot, 256), 256>>>(rows_sr, rows_tg, E0, Etot, n0, ntot);

    // ---- join: attr encoder needs valW ----
    cudaStreamWaitEvent(0, ev_join, 0);
    attr_agg_all_k<<<ntot, 64>>>(tri_sr, tri_tg, ne0, a_b, ent_sr, ent_tg, n0);

    // ---- stacked GCN layers (single-term fp16 A) ----
    dim3 ggrid(2, ceildiv(ntot, 128));
    gcn_agg_h_k<<<ntot, 64>>>(cols_sr, cols_tg, E0, n0, xaH);
    mma_gemm_k<1, 1, 1><<<ggrid, 256>>>(xaH, nullptr, 256, 256, w1t, ntot, b1, F1, F2, Fh);
    gcn_agg_h_k<<<ntot, 64>>>(cols_sr, cols_tg, E0, n0, xaH);
    mma_gemm_k<2, 1, 1><<<ggrid, 256>>>(xaH, nullptr, 256, 256, w2t, ntot, b2, F2, F1, nullptr);

    // ---- output ----
    l2norm_all_k<<<ntot, 64>>>(F1, out_full);
    gather_all_k<<<2 * nseed, 64>>>(seed_sr, seed_tg, nseed, n0, out_full, out_seed);
}

// round 16
// speedup vs baseline: 1.4162x; 1.0418x over previous
#include <cuda_runtime.h>
#include <cuda_fp16.h>
#include <math.h>
#include <stdint.h>

#define DIM 256
#define NTOT 100000
#define ETRI 400000
#define NVALMAX 100000
#define NATTMAX 1001
#define KPAD_VAL 320
#define MT_S 40   // smem row stride in fp16 (80B): conflict-free for ldmatrix 8-row phases

// ---------------- scratch ----------------
__device__ __half g_valW[NVALMAX * DIM];
__device__ __half g_attW[NATTMAX * DIM];
__device__ float g_attdot[NATTMAX];
__device__ float g_entdot[NTOT];
__device__ int   g_cnt[NTOT];
__device__ int   g_ptr[NTOT + 1];
__device__ int   g_eptr[NTOT + 1];
__device__ int   g_fill[NTOT];
__device__ int   g_idx[ETRI];
__device__ int   g_bsum[128];
__device__ int   g_boff[128];
__device__ float g_F1[NTOT * DIM];
__device__ float g_F2[NTOT * DIM];
__device__ __half g_Fh[NTOT * DIM];      // fp16 copy of current agg input
__device__ __half g_xa_h[NTOT * DIM];    // fp16 A operand for GCN GEMMs
__device__ __half g_wet[DIM * KPAD_VAL];
__device__ __half g_w1t[DIM * DIM];
__device__ __half g_w2t[DIM * DIM];

// ---------------- mma.sync + ldmatrix wrappers ----------------
__device__ __forceinline__ void mma16816(float* c, const uint32_t* a, const uint32_t* b) {
    asm volatile(
        "mma.sync.aligned.m16n8k16.row.col.f32.f16.f16.f32 "
        "{%0,%1,%2,%3}, {%4,%5,%6,%7}, {%8,%9}, {%0,%1,%2,%3};"
        : "+f"(c[0]), "+f"(c[1]), "+f"(c[2]), "+f"(c[3])
        : "r"(a[0]), "r"(a[1]), "r"(a[2]), "r"(a[3]), "r"(b[0]), "r"(b[1]));
}
#define LDMX4(r0, r1, r2, r3, addr) \
    asm volatile("ldmatrix.sync.aligned.m8n8.x4.shared.b16 {%0,%1,%2,%3}, [%4];" \
        : "=r"(r0), "=r"(r1), "=r"(r2), "=r"(r3) : "r"(addr))

// ---------------- HMMA fp16 GEMM: 128x128 CTA, 8 warps of 32x64 --------------
// TERMS=2: A = Ah + Al (fp16 pair); TERMS=1: A = Ah only. B = Bh fp16. fp32 accum.
// PRE=0: A fp32 converted in-register; PRE=1: A pre-split fp16.
// MODE 0: Ch = AB (fp16 out) ; MODE 1: C = res + relu(AB+bias), Ch = fp16 copy ;
// MODE 2: C = res + AB + bias
template <int MODE, int PRE, int TERMS>
__global__ void __launch_bounds__(256, 2)
mma_gemm_k(const void* __restrict__ Ap, const void* __restrict__ Ap2, int K, int Kpad,
           const __half* __restrict__ Bh, int M,
           const float* __restrict__ bias, const float* __restrict__ res,
           float* __restrict__ C, __half* __restrict__ Ch) {
    __shared__ __align__(16) __half sAh[128 * MT_S];
    __shared__ __align__(16) __half sAl[TERMS == 2 ? 128 * MT_S : 8];
    __shared__ __align__(16) __half sBh[128 * MT_S];
    int tid = threadIdx.x;
    int wid = tid >> 5, lane = tid & 31;
    int wm = wid & 3;
    int wn = wid >> 2;
    int row0 = blockIdx.y * 128;
    int col0 = blockIdx.x * 128;

    uint32_t sAh_b = (uint32_t)__cvta_generic_to_shared(sAh);
    uint32_t sAl_b = (uint32_t)__cvta_generic_to_shared(sAl);
    uint32_t sBh_b = (uint32_t)__cvta_generic_to_shared(sBh);

    float acc[2][8][4];
    #pragma unroll
    for (int mt = 0; mt < 2; mt++)
        #pragma unroll
        for (int nt = 0; nt < 8; nt++)
            #pragma unroll
            for (int q = 0; q < 4; q++) acc[mt][nt][q] = 0.f;

    int lr = tid >> 1;
    int seg = (tid & 1) * 16;
    int gr = row0 + lr;
    bool arow_ok = gr < M;
    const float* Arow = (const float*)Ap + (size_t)(arow_ok ? gr : 0) * K;
    const __half* AhRow = (const __half*)Ap + (size_t)(arow_ok ? gr : 0) * Kpad;
    const __half* AlRow = (const __half*)Ap2 + (size_t)(arow_ok ? gr : 0) * Kpad;
    const __half* BhRow = Bh + (size_t)(col0 + lr) * Kpad;

    float aF[16];
    uint4 ah[2], al[2];
    uint4 bh[2];

    auto loadChunk = [&](int k0) {
        if (PRE) {
            ah[0] = *(const uint4*)(AhRow + k0 + seg);
            ah[1] = *(const uint4*)(AhRow + k0 + seg + 8);
            if (TERMS == 2) {
                al[0] = *(const uint4*)(AlRow + k0 + seg);
                al[1] = *(const uint4*)(AlRow + k0 + seg + 8);
            }
        } else {
            #pragma unroll
            for (int j = 0; j < 4; j++) {
                int gk = k0 + seg + j * 4;
                float4 v = make_float4(0.f, 0.f, 0.f, 0.f);
                if (arow_ok && gk + 3 < K) v = *(const float4*)(Arow + gk);
                else if (arow_ok) {
                    float tmp[4] = {0.f, 0.f, 0.f, 0.f};
                    #pragma unroll
                    for (int u = 0; u < 4; u++) if (gk + u < K) tmp[u] = Arow[gk + u];
                    v = make_float4(tmp[0], tmp[1], tmp[2], tmp[3]);
                }
                aF[j * 4 + 0] = v.x; aF[j * 4 + 1] = v.y;
                aF[j * 4 + 2] = v.z; aF[j * 4 + 3] = v.w;
            }
        }
        bh[0] = *(const uint4*)(BhRow + k0 + seg);
        bh[1] = *(const uint4*)(BhRow + k0 + seg + 8);
    };
    auto storeChunk = [&]() {
        if (PRE) {
            *(uint4*)&sAh[lr * MT_S + seg]     = ah[0];
            *(uint4*)&sAh[lr * MT_S + seg + 8] = ah[1];
            if (TERMS == 2) {
                *(uint4*)&sAl[lr * MT_S + seg]     = al[0];
                *(uint4*)&sAl[lr * MT_S + seg + 8] = al[1];
            }
        } else {
            __half h[16];
            #pragma unroll
            for (int j = 0; j < 16; j++) h[j] = __float2half(aF[j]);
            *(uint4*)&sAh[lr * MT_S + seg]     = ((const uint4*)h)[0];
            *(uint4*)&sAh[lr * MT_S + seg + 8] = ((const uint4*)h)[1];
            if (TERMS == 2) {
                __half l[16];
                #pragma unroll
                for (int j = 0; j < 16; j++)
                    l[j] = __float2half(aF[j] - __half2float(h[j]));
                *(uint4*)&sAl[lr * MT_S + seg]     = ((const uint4*)l)[0];
                *(uint4*)&sAl[lr * MT_S + seg + 8] = ((const uint4*)l)[1];
            }
        }
        *(uint4*)&sBh[lr * MT_S + seg]     = bh[0];
        *(uint4*)&sBh[lr * MT_S + seg + 8] = bh[1];
    };

    int a_row = wm * 32 + (lane & 15);
    int a_colsel = (lane >> 4) * 8;
    int b_row = wn * 64 + ((lane >> 4) ? 8 : 0) + (lane & 7);
    int b_colsel = ((lane >> 3) & 1) * 8;

    int nch = Kpad / 32;
    loadChunk(0);
    for (int ci = 0; ci < nch; ci++) {
        storeChunk();
        __syncthreads();
        if (ci + 1 < nch) loadChunk((ci + 1) * 32);
        #pragma unroll
        for (int ks = 0; ks < 2; ks++) {
            uint32_t aH[2][4], aL[2][4];
            #pragma unroll
            for (int mt = 0; mt < 2; mt++) {
                uint32_t off = (uint32_t)(((a_row + mt * 16) * MT_S + ks * 16 + a_colsel) * 2);
                LDMX4(aH[mt][0], aH[mt][1], aH[mt][2], aH[mt][3], sAh_b + off);
                if (TERMS == 2)
                    LDMX4(aL[mt][0], aL[mt][1], aL[mt][2], aL[mt][3], sAl_b + off);
            }
            #pragma unroll
            for (int p = 0; p < 4; p++) {
                uint32_t off = (uint32_t)(((b_row + p * 16) * MT_S + ks * 16 + b_colsel) * 2);
                uint32_t h0, h1, h2, h3;
                LDMX4(h0, h1, h2, h3, sBh_b + off);
                uint32_t bH0[2] = {h0, h1}, bH1[2] = {h2, h3};
                #pragma unroll
                for (int mt = 0; mt < 2; mt++) {
                    mma16816(acc[mt][2 * p],     aH[mt], bH0);
                    mma16816(acc[mt][2 * p + 1], aH[mt], bH1);
                    if (TERMS == 2) {
                        mma16816(acc[mt][2 * p],     aL[mt], bH0);
                        mma16816(acc[mt][2 * p + 1], aL[mt], bH1);
                    }
                }
            }
        }
        __syncthreads();
    }

    #pragma unroll
    for (int mt = 0; mt < 2; mt++) {
        #pragma unroll
        for (int half = 0; half < 2; half++) {
            int r = row0 + wm * 32 + mt * 16 + (lane >> 2) + half * 8;
            if (r >= M) continue;
            #pragma unroll
            for (int nt = 0; nt < 8; nt++) {
                int c = col0 + wn * 64 + nt * 8 + (lane & 3) * 2;
                float2 v;
                v.x = acc[mt][nt][half * 2 + 0];
                v.y = acc[mt][nt][half * 2 + 1];
                if (MODE >= 1) {
                    const float2 bb = *(const float2*)&bias[c];
                    v.x += bb.x; v.y += bb.y;
                    if (MODE == 1) { v.x = fmaxf(v.x, 0.f); v.y = fmaxf(v.y, 0.f); }
                    const float2 rr = *(const float2*)&res[(size_t)r * 256 + c];
                    v.x += rr.x; v.y += rr.y;
                }
                if (MODE != 0) *(float2*)&C[(size_t)r * 256 + c] = v;
                if (MODE != 2) {
                    __half2 hv = __floats2half2_rn(v.x, v.y);
                    *(__half2*)&Ch[(size_t)r * 256 + c] = hv;
                }
            }
        }
    }
}

// ---------------- weight transpose to fp16 ----------------
__global__ void tsplit_h_k(const float* __restrict__ src, int K, int Kpad,
                           __half* __restrict__ hi) {
    int idx = blockIdx.x * blockDim.x + threadIdx.x;
    if (idx >= 256 * Kpad) return;
    int k = idx % Kpad;
    int n = idx / Kpad;
    float v = (k < K) ? src[(size_t)k * 256 + n] : 0.f;
    hi[idx] = __float2half(v);
}

// ---------------- stacked SIMT pipeline kernels ----------------
__global__ void zero_int_k(int* p, int n) {
    int i = blockIdx.x * blockDim.x + threadIdx.x;
    if (i < n) p[i] = 0;
}
__global__ void att_k(const float* __restrict__ att_feats,
                      const float* __restrict__ W_enc,
                      const float* __restrict__ a_w, int natt) {
    int r = blockIdx.x;
    int d = threadIdx.x;
    __shared__ float sh[DIM];
    __shared__ float sred[8];
    sh[d] = att_feats[(size_t)r * DIM + d];
    __syncthreads();
    float acc = 0.f;
    #pragma unroll 8
    for (int k = 0; k < DIM; k++) acc += sh[k] * W_enc[(size_t)k * DIM + d];
    g_attW[(size_t)r * DIM + d] = __float2half(acc);
    float v = sh[d] * a_w[DIM + d];
    for (int o = 16; o; o >>= 1) v += __shfl_xor_sync(0xffffffffu, v, o);
    if ((d & 31) == 0) sred[d >> 5] = v;
    __syncthreads();
    if (d == 0) {
        float s = 0.f;
        #pragma unroll
        for (int i = 0; i < 8; i++) s += sred[i];
        g_attdot[r] = s;
    }
}
__global__ void entdot_all_k(const float* __restrict__ ent0, const float* __restrict__ ent1,
                             const float* __restrict__ a_w, int n0, int ntot) {
    int node = (blockIdx.x * blockDim.x + threadIdx.x) >> 5;
    int lane = threadIdx.x & 31;
    if (node >= ntot) return;
    const float* row = (node < n0) ? ent0 + (size_t)node * DIM
                                   : ent1 + (size_t)(node - n0) * DIM;
    float s = 0.f;
    #pragma unroll
    for (int d = lane; d < DIM; d += 32) s += row[d] * a_w[d];
    for (int o = 16; o; o >>= 1) s += __shfl_xor_sync(0xffffffffu, s, o);
    if (lane == 0) g_entdot[node] = s;
}
__global__ void hist_tri_all_k(const int* __restrict__ t0, const int* __restrict__ t1,
                               int ne0, int netot, int n0) {
    int e = blockIdx.x * blockDim.x + threadIdx.x;
    if (e >= netot) return;
    int head = (e < ne0) ? t0[3 * e] : n0 + t1[3 * (e - ne0)];
    atomicAdd(&g_cnt[head], 1);
}
__global__ void scan_blk_k(int n) {
    __shared__ int wsum[32];
    int b = blockIdx.x;
    int i = b * 1024 + threadIdx.x;
    int lane = threadIdx.x & 31, wid = threadIdx.x >> 5;
    int v = (i < n) ? g_cnt[i] : 0;
    int x = v;
    #pragma unroll
    for (int o = 1; o < 32; o <<= 1) {
        int y = __shfl_up_sync(0xffffffffu, x, o);
        if (lane >= o) x += y;
    }
    if (lane == 31) wsum[wid] = x;
    __syncthreads();
    if (wid == 0) {
        int w = wsum[lane];
        int xs = w;
        #pragma unroll
        for (int o = 1; o < 32; o <<= 1) {
            int y = __shfl_up_sync(0xffffffffu, xs, o);
            if (lane >= o) xs += y;
        }
        wsum[lane] = xs - w;
    }
    __syncthreads();
    int excl = wsum[wid] + x - v;
    if (i < n) g_ptr[i] = excl;
    if (threadIdx.x == 1023) g_bsum[b] = excl + v;
}
__global__ void scan_mid_k(int nb, int n) {
    int lane = threadIdx.x;
    int carry = 0;
    for (int base = 0; base < nb; base += 32) {
        int i = base + lane;
        int v = (i < nb) ? g_bsum[i] : 0;
        int x = v;
        #pragma unroll
        for (int o = 1; o < 32; o <<= 1) {
            int y = __shfl_up_sync(0xffffffffu, x, o);
            if (lane >= o) x += y;
        }
        if (i < nb) g_boff[i] = carry + x - v;
        carry += __shfl_sync(0xffffffffu, x, 31);
    }
    if (lane == 0) g_ptr[n] = carry;
}
__global__ void scan_add_k(int n) {
    int i = blockIdx.x * blockDim.x + threadIdx.x;
    if (i < n) {
        int p = g_ptr[i] + g_boff[i >> 10];
        g_ptr[i] = p;
        g_fill[i] = p;
    }
}
__global__ void scatter_tri_all_k(const int* __restrict__ t0, const int* __restrict__ t1,
                                  int ne0, int netot, int n0) {
    int e = blockIdx.x * blockDim.x + threadIdx.x;
    if (e >= netot) return;
    int head = (e < ne0) ? t0[3 * e] : n0 + t1[3 * (e - ne0)];
    int pos = atomicAdd(&g_fill[head], 1);
    g_idx[pos] = e;
}
__global__ void edge_ptr_all_k(const int* __restrict__ r0, const int* __restrict__ r1,
                               int E0, int Etot, int n0, int ntot) {
    int e = blockIdx.x * blockDim.x + threadIdx.x;
    if (e >= Etot) return;
    int r = (e < E0) ? r0[e] : n0 + r1[e - E0];
    if (e == 0) {
        for (int v = 0; v <= r; v++) g_eptr[v] = 0;
    } else {
        int rp = (e - 1 < E0) ? r0[e - 1] : n0 + r1[e - 1 - E0];
        for (int v = rp + 1; v <= r; v++) g_eptr[v] = e;
    }
    if (e == Etot - 1) {
        for (int v = r + 1; v <= ntot; v++) g_eptr[v] = Etot;
    }
}
// attributed encoder: pass1 softmax denom; pass2 split-table gather (uint4 rows)
__global__ void attr_agg_all_k(const int* __restrict__ t0, const int* __restrict__ t1,
                               int ne0,
                               const float* __restrict__ ab_ptr,
                               const float* __restrict__ ent0, const float* __restrict__ ent1,
                               int n0) {
    int v = blockIdx.x;
    int t = threadIdx.x;          // 0..63
    int half_id = t >> 5;
    int ld = (t & 31) * 8;
    int s = g_ptr[v], e = g_ptr[v + 1];
    int side = v >= n0;
    const int* tri = side ? t1 : t0;
    int tbase = side ? ne0 : 0;
    __shared__ float sred[2];
    __shared__ float s_inv;
    __shared__ float sh_p[64];
    __shared__ int sh_att[64];
    __shared__ int sh_val[64];
    __shared__ float sh_acc[32][8];
    float ab = ab_ptr[0];
    float ed = g_entdot[v];
    float part = 0.f;
    for (int i = s + t; i < e; i += 64) {
        int tt = g_idx[i] - tbase;
        float sc = ed + g_attdot[tri[3 * tt + 2]] + ab;
        sc = sc > 0.f ? sc : 0.2f * sc;
        part += expf(sc);
    }
    for (int o = 16; o; o >>= 1) part += __shfl_xor_sync(0xffffffffu, part, o);
    if ((t & 31) == 0) sred[t >> 5] = part;
    __syncthreads();
    if (t == 0) {
        float rs = sred[0] + sred[1];
        s_inv = (rs > 0.f) ? 1.f / rs : 0.f;
    }
    __syncthreads();
    float inv_rs = s_inv;
    float acc[8] = {0.f, 0.f, 0.f, 0.f, 0.f, 0.f, 0.f, 0.f};
    const __half* table = half_id ? g_valW : g_attW;
    for (int base = s; base < e; base += 64) {
        int cnt = min(64, e - base);
        if (t < cnt) {
            int tt = g_idx[base + t] - tbase;
            sh_att[t] = tri[3 * tt + 2];
            sh_val[t] = tri[3 * tt + 1];
            float sc = ed + g_attdot[sh_att[t]] + ab;
            sc = sc > 0.f ? sc : 0.2f * sc;
            sh_p[t] = expf(sc) * inv_rs;
        }
        __syncthreads();
        for (int j = 0; j < cnt; j++) {
            int row = half_id ? sh_val[j] : sh_att[j];
            float p = sh_p[j];
            uint4 u = *(const uint4*)&table[(size_t)row * DIM + ld];
            const __half2* hp = (const __half2*)&u;
            #pragma unroll
            for (int q = 0; q < 4; q++) {
                float2 f = __half22float2(hp[q]);
                acc[2 * q]     += p * f.x;
                acc[2 * q + 1] += p * f.y;
            }
        }
        __syncthreads();
    }
    if (half_id == 1) {
        #pragma unroll
        for (int q = 0; q < 8; q++) sh_acc[t & 31][q] = acc[q];
    }
    __syncthreads();
    if (half_id == 0) {
        const float* ef_row = side ? ent1 + (size_t)(v - n0) * DIM : ent0 + (size_t)v * DIM;
        float4 e0 = *(const float4*)&ef_row[ld];
        float4 e1 = *(const float4*)&ef_row[ld + 4];
        float ef[8] = {e0.x, e0.y, e0.z, e0.w, e1.x, e1.y, e1.z, e1.w};
        float outv[8];
        __half h8[8];
        #pragma unroll
        for (int q = 0; q < 8; q++) {
            float x = acc[q] + sh_acc[t][q] + ef[q];
            x = x > 0.f ? x : expm1f(x);
            outv[q] = x;
            h8[q] = __float2half(x);
        }
        *(float4*)&g_F1[(size_t)v * DIM + ld]     = make_float4(outv[0], outv[1], outv[2], outv[3]);
        *(float4*)&g_F1[(size_t)v * DIM + ld + 4] = make_float4(outv[4], outv[5], outv[6], outv[7]);
        *(uint4*)&g_Fh[(size_t)v * DIM + ld] = *(uint4*)h8;
    }
}
// GCN mean-agg: warp-halves take alternating neighbors; uint4 fp16 row loads
__global__ void gcn_agg_h_k(const int* __restrict__ c0, const int* __restrict__ c1,
                            int E0, int n0, __half* __restrict__ outh) {
    int v = blockIdx.x;
    int t = threadIdx.x;
    int half_id = t >> 5;
    int ld = (t & 31) * 8;
    int s = g_eptr[v], e = g_eptr[v + 1];
    __shared__ int sh_c[64];
    __shared__ float sh_acc[32][8];
    float acc[8] = {0.f, 0.f, 0.f, 0.f, 0.f, 0.f, 0.f, 0.f};
    for (int base = s; base < e; base += 64) {
        int cnt = min(64, e - base);
        if (t < cnt) {
            int i = base + t;
            sh_c[t] = (i < E0) ? c0[i] : n0 + c1[i - E0];
        }
        __syncthreads();
        for (int j = half_id; j < cnt; j += 2) {
            uint4 u = *(const uint4*)&g_Fh[(size_t)sh_c[j] * DIM + ld];
            const __half2* hp = (const __half2*)&u;
            #pragma unroll
            for (int q = 0; q < 4; q++) {
                float2 f = __half22float2(hp[q]);
                acc[2 * q]     += f.x;
                acc[2 * q + 1] += f.y;
            }
        }
        __syncthreads();
    }
    if (half_id == 1) {
        #pragma unroll
        for (int q = 0; q < 8; q++) sh_acc[t & 31][q] = acc[q];
    }
    __syncthreads();
    if (half_id == 0) {
        float inv = (e > s) ? 1.f / (float)(e - s) : 0.f;
        __half h8[8];
        #pragma unroll
        for (int q = 0; q < 8; q++)
            h8[q] = __float2half((acc[q] + sh_acc[t][q]) * inv);
        *(uint4*)&outh[(size_t)v * DIM + ld] = *(uint4*)h8;
    }
}
__global__ void l2norm_all_k(const float* __restrict__ in, float* __restrict__ out) {
    int v = blockIdx.x;
    int t = threadIdx.x;
    __shared__ float sred[2];
    __shared__ float s_inv;
    const float4 x = *(const float4*)&in[(size_t)v * DIM + t * 4];
    float sq = x.x * x.x + x.y * x.y + x.z * x.z + x.w * x.w;
    for (int o = 16; o; o >>= 1) sq += __shfl_xor_sync(0xffffffffu, sq, o);
    if ((t & 31) == 0) sred[t >> 5] = sq;
    __syncthreads();
    if (t == 0) {
        float nrm = sqrtf(sred[0] + sred[1]);
        s_inv = 1.f / fmaxf(nrm, 1e-12f);
    }
    __syncthreads();
    float inv = s_inv;
    float4 y = make_float4(x.x * inv, x.y * inv, x.z * inv, x.w * inv);
    *(float4*)&out[(size_t)v * DIM + t * 4] = y;
}
__global__ void gather_all_k(const int* __restrict__ s0, const int* __restrict__ s1,
                             int nseed, int n0,
                             const float* __restrict__ src, float* __restrict__ dst) {
    int i = blockIdx.x;
    int t = threadIdx.x;
    int node = (i < nseed) ? s0[i] : n0 + s1[i - nseed];
    *(float4*)&dst[(size_t)i * DIM + t * 4] =
        *(const float4*)&src[(size_t)node * DIM + t * 4];
}

// ---------------- host orchestration ----------------
static inline int ceildiv(int a, int b) { return (a + b - 1) / b; }

extern "C" void kernel_launch(void* const* d_in, const int* in_sizes, int n_in,
                              void* d_out, int out_size) {
    const int* seed_sr = (const int*)d_in[0];
    const int* seed_tg = (const int*)d_in[1];
    const int* tri_sr  = (const int*)d_in[2];
    const int* tri_tg  = (const int*)d_in[3];
    const int* rows_sr = (const int*)d_in[4];
    const int* cols_sr = (const int*)d_in[5];
    const int* rows_tg = (const int*)d_in[6];
    const int* cols_tg = (const int*)d_in[7];
    const float* att_feats = (const float*)d_in[8];
    const float* val_feats = (const float*)d_in[9];
    const float* ent_sr = (const float*)d_in[10];
    const float* ent_tg = (const float*)d_in[11];
    const float* a_w   = (const float*)d_in[12];
    const float* a_b   = (const float*)d_in[13];
    const float* W_enc = (const float*)d_in[14];
    const float* w1    = (const float*)d_in[15];
    const float* b1    = (const float*)d_in[16];
    const float* w2    = (const float*)d_in[17];
    const float* b2    = (const float*)d_in[18];
    (void)n_in; (void)out_size;

    const int nseed  = in_sizes[0];
    const int ne0    = in_sizes[2] / 3;
    const int ne1    = in_sizes[3] / 3;
    const int E0     = in_sizes[4];
    const int E1     = in_sizes[6];
    const int natt   = in_sizes[8] / DIM;
    const int nval   = in_sizes[9] / 300;
    const int n0     = in_sizes[10] / DIM;
    const int n1     = in_sizes[11] / DIM;
    const int ntot   = n0 + n1;
    const int netot  = ne0 + ne1;
    const int Etot   = E0 + E1;

    static cudaStream_t s_aux = nullptr;
    static cudaEvent_t ev_fork = nullptr, ev_join = nullptr;
    if (!s_aux) {
        cudaStreamCreateWithFlags(&s_aux, cudaStreamNonBlocking);
        cudaEventCreateWithFlags(&ev_fork, cudaEventDisableTiming);
        cudaEventCreateWithFlags(&ev_join, cudaEventDisableTiming);
    }

    __half* valW; cudaGetSymbolAddress((void**)&valW, g_valW);
    float* F1;    cudaGetSymbolAddress((void**)&F1,   g_F1);
    float* F2;    cudaGetSymbolAddress((void**)&F2,   g_F2);
    __half* Fh;   cudaGetSymbolAddress((void**)&Fh,   g_Fh);
    int*   cntp;  cudaGetSymbolAddress((void**)&cntp, g_cnt);
    __half *xaH, *wet, *w1t, *w2t;
    cudaGetSymbolAddress((void**)&xaH, g_xa_h);
    cudaGetSymbolAddress((void**)&wet, g_wet);
    cudaGetSymbolAddress((void**)&w1t, g_w1t);
    cudaGetSymbolAddress((void**)&w2t, g_w2t);

    float* out = (float*)d_out;
    float* out_seed = out;
    float* out_full = out + (size_t)2 * nseed * DIM;

    // ---- precompute; valW GEMM (1-term A, fp16 out) forked to aux stream ----
    tsplit_h_k<<<ceildiv(256 * KPAD_VAL, 256), 256>>>(
        W_enc + (size_t)DIM * DIM, 300, KPAD_VAL, wet);
    cudaEventRecord(ev_fork, 0);
    cudaStreamWaitEvent(s_aux, ev_fork, 0);
    {
        dim3 grid(2, ceildiv(nval, 128));
        mma_gemm_k<0, 0, 1><<<grid, 256, 0, s_aux>>>(
            val_feats, nullptr, 300, KPAD_VAL, wet, nval, nullptr, nullptr, nullptr, valW);
    }
    cudaEventRecord(ev_join, s_aux);
    att_k<<<natt, DIM>>>(att_feats, W_enc, a_w, natt);
    tsplit_h_k<<<ceildiv(256 * 256, 256), 256>>>(w1, 256, 256, w1t);
    tsplit_h_k<<<ceildiv(256 * 256, 256), 256>>>(w2, 256, 256, w2t);
    entdot_all_k<<<ceildiv(ntot * 32, 256), 256>>>(ent_sr, ent_tg, a_w, n0, ntot);
    zero_int_k<<<ceildiv(ntot, 256), 256>>>(cntp, ntot);
    hist_tri_all_k<<<ceildiv(netot, 256), 256>>>(tri_sr, tri_tg, ne0, netot, n0);
    int nb = ceildiv(ntot, 1024);
    scan_blk_k<<<nb, 1024>>>(ntot);
    scan_mid_k<<<1, 32>>>(nb, ntot);
    scan_add_k<<<ceildiv(ntot, 256), 256>>>(ntot);
    scatter_tri_all_k<<<ceildiv(netot, 256), 256>>>(tri_sr, tri_tg, ne0, netot, n0);
    edge_ptr_all_k<<<ceildiv(Etot, 256), 256>>>(rows_sr, rows_tg, E0, Etot, n0, ntot);

    // ---- join: attr encoder needs valW ----
    cudaStreamWaitEvent(0, ev_join, 0);
    attr_agg_all_k<<<ntot, 64>>>(tri_sr, tri_tg, ne0, a_b, ent_sr, ent_tg, n0);

    // ---- stacked GCN layers (single-term fp16 A) ----
    dim3 ggrid(2, ceildiv(ntot, 128));
    gcn_agg_h_k<<<ntot, 64>>>(cols_sr, cols_tg, E0, n0, xaH);
    mma_gemm_k<1, 1, 1><<<ggrid, 256>>>(xaH, nullptr, 256, 256, w1t, ntot, b1, F1, F2, Fh);
    gcn_agg_h_k<<<ntot, 64>>>(cols_sr, cols_tg, E0, n0, xaH);
    mma_gemm_k<2, 1, 1><<<ggrid, 256>>>(xaH, nullptr, 256, 256, w2t, ntot, b2, F2, F1, nullptr);

    // ---- output ----
    l2norm_all_k<<<ntot, 64>>>(F1, out_full);
    gather_all_k<<<2 * nseed, 64>>>(seed_sr, seed_tg, nseed, n0, out_full, out_seed);
}

// round 17
// speedup vs baseline: 1.5027x; 1.0611x over previous
#include <cuda_runtime.h>
#include <cuda_fp16.h>
#include <math.h>
#include <stdint.h>

#define DIM 256
#define NTOT 100000
#define ETRI 400000
#define NVALMAX 100000
#define NATTMAX 1001
#define KPAD_VAL 320
#define MT_S 40   // smem row stride in fp16 (80B): conflict-free for ldmatrix 8-row phases

// ---------------- scratch ----------------
__device__ __half g_valW[NVALMAX * DIM];
__device__ __half g_attW[NATTMAX * DIM];
__device__ float g_attdot[NATTMAX];
__device__ float g_entdot[NTOT];
__device__ int   g_cnt[NTOT];
__device__ int   g_ptr[NTOT + 1];
__device__ int   g_eptr[NTOT + 1];
__device__ int   g_fill[NTOT];
__device__ int   g_idx[ETRI];
__device__ int   g_bsum[128];
__device__ int   g_boff[128];
__device__ float g_F1[NTOT * DIM];
__device__ float g_F2[NTOT * DIM];
__device__ __half g_Fh[NTOT * DIM];
__device__ __half g_xa_h[NTOT * DIM];
__device__ __half g_wet[DIM * KPAD_VAL];
__device__ __half g_w1t[DIM * DIM];
__device__ __half g_w2t[DIM * DIM];

// ---------------- mma.sync + ldmatrix wrappers ----------------
__device__ __forceinline__ void mma16816(float* c, const uint32_t* a, const uint32_t* b) {
    asm volatile(
        "mma.sync.aligned.m16n8k16.row.col.f32.f16.f16.f32 "
        "{%0,%1,%2,%3}, {%4,%5,%6,%7}, {%8,%9}, {%0,%1,%2,%3};"
        : "+f"(c[0]), "+f"(c[1]), "+f"(c[2]), "+f"(c[3])
        : "r"(a[0]), "r"(a[1]), "r"(a[2]), "r"(a[3]), "r"(b[0]), "r"(b[1]));
}
#define LDMX4(r0, r1, r2, r3, addr) \
    asm volatile("ldmatrix.sync.aligned.m8n8.x4.shared.b16 {%0,%1,%2,%3}, [%4];" \
        : "=r"(r0), "=r"(r1), "=r"(r2), "=r"(r3) : "r"(addr))

__device__ __forceinline__ void acc_u4(float* acc, uint4 u, float p) {
    const __half2* hp = (const __half2*)&u;
    #pragma unroll
    for (int q = 0; q < 4; q++) {
        float2 f = __half22float2(hp[q]);
        acc[2 * q]     += p * f.x;
        acc[2 * q + 1] += p * f.y;
    }
}
__device__ __forceinline__ void acc_u4n(float* acc, uint4 u) {
    const __half2* hp = (const __half2*)&u;
    #pragma unroll
    for (int q = 0; q < 4; q++) {
        float2 f = __half22float2(hp[q]);
        acc[2 * q]     += f.x;
        acc[2 * q + 1] += f.y;
    }
}

// ---------------- HMMA fp16 GEMM: 128x128 CTA, 8 warps of 32x64 --------------
template <int MODE, int PRE, int TERMS>
__global__ void __launch_bounds__(256, 2)
mma_gemm_k(const void* __restrict__ Ap, const void* __restrict__ Ap2, int K, int Kpad,
           const __half* __restrict__ Bh, int M,
           const float* __restrict__ bias, const float* __restrict__ res,
           float* __restrict__ C, __half* __restrict__ Ch) {
    __shared__ __align__(16) __half sAh[128 * MT_S];
    __shared__ __align__(16) __half sAl[TERMS == 2 ? 128 * MT_S : 8];
    __shared__ __align__(16) __half sBh[128 * MT_S];
    int tid = threadIdx.x;
    int wid = tid >> 5, lane = tid & 31;
    int wm = wid & 3;
    int wn = wid >> 2;
    int row0 = blockIdx.y * 128;
    int col0 = blockIdx.x * 128;

    uint32_t sAh_b = (uint32_t)__cvta_generic_to_shared(sAh);
    uint32_t sAl_b = (uint32_t)__cvta_generic_to_shared(sAl);
    uint32_t sBh_b = (uint32_t)__cvta_generic_to_shared(sBh);

    float acc[2][8][4];
    #pragma unroll
    for (int mt = 0; mt < 2; mt++)
        #pragma unroll
        for (int nt = 0; nt < 8; nt++)
            #pragma unroll
            for (int q = 0; q < 4; q++) acc[mt][nt][q] = 0.f;

    int lr = tid >> 1;
    int seg = (tid & 1) * 16;
    int gr = row0 + lr;
    bool arow_ok = gr < M;
    const float* Arow = (const float*)Ap + (size_t)(arow_ok ? gr : 0) * K;
    const __half* AhRow = (const __half*)Ap + (size_t)(arow_ok ? gr : 0) * Kpad;
    const __half* AlRow = (const __half*)Ap2 + (size_t)(arow_ok ? gr : 0) * Kpad;
    const __half* BhRow = Bh + (size_t)(col0 + lr) * Kpad;

    float aF[16];
    uint4 ah[2], al[2];
    uint4 bh[2];

    auto loadChunk = [&](int k0) {
        if (PRE) {
            ah[0] = *(const uint4*)(AhRow + k0 + seg);
            ah[1] = *(const uint4*)(AhRow + k0 + seg + 8);
            if (TERMS == 2) {
                al[0] = *(const uint4*)(AlRow + k0 + seg);
                al[1] = *(const uint4*)(AlRow + k0 + seg + 8);
            }
        } else {
            #pragma unroll
            for (int j = 0; j < 4; j++) {
                int gk = k0 + seg + j * 4;
                float4 v = make_float4(0.f, 0.f, 0.f, 0.f);
                if (arow_ok && gk + 3 < K) v = *(const float4*)(Arow + gk);
                else if (arow_ok) {
                    float tmp[4] = {0.f, 0.f, 0.f, 0.f};
                    #pragma unroll
                    for (int u = 0; u < 4; u++) if (gk + u < K) tmp[u] = Arow[gk + u];
                    v = make_float4(tmp[0], tmp[1], tmp[2], tmp[3]);
                }
                aF[j * 4 + 0] = v.x; aF[j * 4 + 1] = v.y;
                aF[j * 4 + 2] = v.z; aF[j * 4 + 3] = v.w;
            }
        }
        bh[0] = *(const uint4*)(BhRow + k0 + seg);
        bh[1] = *(const uint4*)(BhRow + k0 + seg + 8);
    };
    auto storeChunk = [&]() {
        if (PRE) {
            *(uint4*)&sAh[lr * MT_S + seg]     = ah[0];
            *(uint4*)&sAh[lr * MT_S + seg + 8] = ah[1];
            if (TERMS == 2) {
                *(uint4*)&sAl[lr * MT_S + seg]     = al[0];
                *(uint4*)&sAl[lr * MT_S + seg + 8] = al[1];
            }
        } else {
            __half h[16];
            #pragma unroll
            for (int j = 0; j < 16; j++) h[j] = __float2half(aF[j]);
            *(uint4*)&sAh[lr * MT_S + seg]     = ((const uint4*)h)[0];
            *(uint4*)&sAh[lr * MT_S + seg + 8] = ((const uint4*)h)[1];
            if (TERMS == 2) {
                __half l[16];
                #pragma unroll
                for (int j = 0; j < 16; j++)
                    l[j] = __float2half(aF[j] - __half2float(h[j]));
                *(uint4*)&sAl[lr * MT_S + seg]     = ((const uint4*)l)[0];
                *(uint4*)&sAl[lr * MT_S + seg + 8] = ((const uint4*)l)[1];
            }
        }
        *(uint4*)&sBh[lr * MT_S + seg]     = bh[0];
        *(uint4*)&sBh[lr * MT_S + seg + 8] = bh[1];
    };

    int a_row = wm * 32 + (lane & 15);
    int a_colsel = (lane >> 4) * 8;
    int b_row = wn * 64 + ((lane >> 4) ? 8 : 0) + (lane & 7);
    int b_colsel = ((lane >> 3) & 1) * 8;

    int nch = Kpad / 32;
    loadChunk(0);
    for (int ci = 0; ci < nch; ci++) {
        storeChunk();
        __syncthreads();
        if (ci + 1 < nch) loadChunk((ci + 1) * 32);
        #pragma unroll
        for (int ks = 0; ks < 2; ks++) {
            uint32_t aH[2][4], aL[2][4];
            #pragma unroll
            for (int mt = 0; mt < 2; mt++) {
                uint32_t off = (uint32_t)(((a_row + mt * 16) * MT_S + ks * 16 + a_colsel) * 2);
                LDMX4(aH[mt][0], aH[mt][1], aH[mt][2], aH[mt][3], sAh_b + off);
                if (TERMS == 2)
                    LDMX4(aL[mt][0], aL[mt][1], aL[mt][2], aL[mt][3], sAl_b + off);
            }
            #pragma unroll
            for (int p = 0; p < 4; p++) {
                uint32_t off = (uint32_t)(((b_row + p * 16) * MT_S + ks * 16 + b_colsel) * 2);
                uint32_t h0, h1, h2, h3;
                LDMX4(h0, h1, h2, h3, sBh_b + off);
                uint32_t bH0[2] = {h0, h1}, bH1[2] = {h2, h3};
                #pragma unroll
                for (int mt = 0; mt < 2; mt++) {
                    mma16816(acc[mt][2 * p],     aH[mt], bH0);
                    mma16816(acc[mt][2 * p + 1], aH[mt], bH1);
                    if (TERMS == 2) {
                        mma16816(acc[mt][2 * p],     aL[mt], bH0);
                        mma16816(acc[mt][2 * p + 1], aL[mt], bH1);
                    }
                }
            }
        }
        __syncthreads();
    }

    #pragma unroll
    for (int mt = 0; mt < 2; mt++) {
        #pragma unroll
        for (int half = 0; half < 2; half++) {
            int r = row0 + wm * 32 + mt * 16 + (lane >> 2) + half * 8;
            if (r >= M) continue;
            #pragma unroll
            for (int nt = 0; nt < 8; nt++) {
                int c = col0 + wn * 64 + nt * 8 + (lane & 3) * 2;
                float2 v;
                v.x = acc[mt][nt][half * 2 + 0];
                v.y = acc[mt][nt][half * 2 + 1];
                if (MODE >= 1) {
                    const float2 bb = *(const float2*)&bias[c];
                    v.x += bb.x; v.y += bb.y;
                    if (MODE == 1) { v.x = fmaxf(v.x, 0.f); v.y = fmaxf(v.y, 0.f); }
                    const float2 rr = *(const float2*)&res[(size_t)r * 256 + c];
                    v.x += rr.x; v.y += rr.y;
                }
                if (MODE != 0) *(float2*)&C[(size_t)r * 256 + c] = v;
                if (MODE != 2) {
                    __half2 hv = __floats2half2_rn(v.x, v.y);
                    *(__half2*)&Ch[(size_t)r * 256 + c] = hv;
                }
            }
        }
    }
}

// ---------------- weight transpose to fp16 ----------------
__global__ void tsplit_h_k(const float* __restrict__ src, int K, int Kpad,
                           __half* __restrict__ hi) {
    int idx = blockIdx.x * blockDim.x + threadIdx.x;
    if (idx >= 256 * Kpad) return;
    int k = idx % Kpad;
    int n = idx / Kpad;
    float v = (k < K) ? src[(size_t)k * 256 + n] : 0.f;
    hi[idx] = __float2half(v);
}

// ---------------- stacked SIMT pipeline kernels ----------------
__global__ void zero_int_k(int* p, int n) {
    int i = blockIdx.x * blockDim.x + threadIdx.x;
    if (i < n) p[i] = 0;
}
__global__ void att_k(const float* __restrict__ att_feats,
                      const float* __restrict__ W_enc,
                      const float* __restrict__ a_w, int natt) {
    int r = blockIdx.x;
    int d = threadIdx.x;
    __shared__ float sh[DIM];
    __shared__ float sred[8];
    sh[d] = att_feats[(size_t)r * DIM + d];
    __syncthreads();
    float acc = 0.f;
    #pragma unroll 8
    for (int k = 0; k < DIM; k++) acc += sh[k] * W_enc[(size_t)k * DIM + d];
    g_attW[(size_t)r * DIM + d] = __float2half(acc);
    float v = sh[d] * a_w[DIM + d];
    for (int o = 16; o; o >>= 1) v += __shfl_xor_sync(0xffffffffu, v, o);
    if ((d & 31) == 0) sred[d >> 5] = v;
    __syncthreads();
    if (d == 0) {
        float s = 0.f;
        #pragma unroll
        for (int i = 0; i < 8; i++) s += sred[i];
        g_attdot[r] = s;
    }
}
__global__ void entdot_all_k(const float* __restrict__ ent0, const float* __restrict__ ent1,
                             const float* __restrict__ a_w, int n0, int ntot) {
    int node = (blockIdx.x * blockDim.x + threadIdx.x) >> 5;
    int lane = threadIdx.x & 31;
    if (node >= ntot) return;
    const float* row = (node < n0) ? ent0 + (size_t)node * DIM
                                   : ent1 + (size_t)(node - n0) * DIM;
    float s = 0.f;
    #pragma unroll
    for (int d = lane; d < DIM; d += 32) s += row[d] * a_w[d];
    for (int o = 16; o; o >>= 1) s += __shfl_xor_sync(0xffffffffu, s, o);
    if (lane == 0) g_entdot[node] = s;
}
__global__ void hist_tri_all_k(const int* __restrict__ t0, const int* __restrict__ t1,
                               int ne0, int netot, int n0) {
    int e = blockIdx.x * blockDim.x + threadIdx.x;
    if (e >= netot) return;
    int head = (e < ne0) ? t0[3 * e] : n0 + t1[3 * (e - ne0)];
    atomicAdd(&g_cnt[head], 1);
}
__global__ void scan_blk_k(int n) {
    __shared__ int wsum[32];
    int b = blockIdx.x;
    int i = b * 1024 + threadIdx.x;
    int lane = threadIdx.x & 31, wid = threadIdx.x >> 5;
    int v = (i < n) ? g_cnt[i] : 0;
    int x = v;
    #pragma unroll
    for (int o = 1; o < 32; o <<= 1) {
        int y = __shfl_up_sync(0xffffffffu, x, o);
        if (lane >= o) x += y;
    }
    if (lane == 31) wsum[wid] = x;
    __syncthreads();
    if (wid == 0) {
        int w = wsum[lane];
        int xs = w;
        #pragma unroll
        for (int o = 1; o < 32; o <<= 1) {
            int y = __shfl_up_sync(0xffffffffu, xs, o);
            if (lane >= o) xs += y;
        }
        wsum[lane] = xs - w;
    }
    __syncthreads();
    int excl = wsum[wid] + x - v;
    if (i < n) g_ptr[i] = excl;
    if (threadIdx.x == 1023) g_bsum[b] = excl + v;
}
__global__ void scan_mid_k(int nb, int n) {
    int lane = threadIdx.x;
    int carry = 0;
    for (int base = 0; base < nb; base += 32) {
        int i = base + lane;
        int v = (i < nb) ? g_bsum[i] : 0;
        int x = v;
        #pragma unroll
        for (int o = 1; o < 32; o <<= 1) {
            int y = __shfl_up_sync(0xffffffffu, x, o);
            if (lane >= o) x += y;
        }
        if (i < nb) g_boff[i] = carry + x - v;
        carry += __shfl_sync(0xffffffffu, x, 31);
    }
    if (lane == 0) g_ptr[n] = carry;
}
__global__ void scan_add_k(int n) {
    int i = blockIdx.x * blockDim.x + threadIdx.x;
    if (i < n) {
        int p = g_ptr[i] + g_boff[i >> 10];
        g_ptr[i] = p;
        g_fill[i] = p;
    }
}
__global__ void scatter_tri_all_k(const int* __restrict__ t0, const int* __restrict__ t1,
                                  int ne0, int netot, int n0) {
    int e = blockIdx.x * blockDim.x + threadIdx.x;
    if (e >= netot) return;
    int head = (e < ne0) ? t0[3 * e] : n0 + t1[3 * (e - ne0)];
    int pos = atomicAdd(&g_fill[head], 1);
    g_idx[pos] = e;
}
__global__ void edge_ptr_all_k(const int* __restrict__ r0, const int* __restrict__ r1,
                               int E0, int Etot, int n0, int ntot) {
    int e = blockIdx.x * blockDim.x + threadIdx.x;
    if (e >= Etot) return;
    int r = (e < E0) ? r0[e] : n0 + r1[e - E0];
    if (e == 0) {
        for (int v = 0; v <= r; v++) g_eptr[v] = 0;
    } else {
        int rp = (e - 1 < E0) ? r0[e - 1] : n0 + r1[e - 1 - E0];
        for (int v = rp + 1; v <= r; v++) g_eptr[v] = e;
    }
    if (e == Etot - 1) {
        for (int v = r + 1; v <= ntot; v++) g_eptr[v] = Etot;
    }
}
// attributed encoder: pass1 softmax denom; pass2 split-table gather, 4x unrolled
__global__ void attr_agg_all_k(const int* __restrict__ t0, const int* __restrict__ t1,
                               int ne0,
                               const float* __restrict__ ab_ptr,
                               const float* __restrict__ ent0, const float* __restrict__ ent1,
                               int n0) {
    int v = blockIdx.x;
    int t = threadIdx.x;
    int half_id = t >> 5;
    int ld = (t & 31) * 8;
    int s = g_ptr[v], e = g_ptr[v + 1];
    int side = v >= n0;
    const int* tri = side ? t1 : t0;
    int tbase = side ? ne0 : 0;
    __shared__ float sred[2];
    __shared__ float s_inv;
    __shared__ float sh_p[64];
    __shared__ int sh_att[64];
    __shared__ int sh_val[64];
    __shared__ float sh_acc[32][8];
    float ab = ab_ptr[0];
    float ed = g_entdot[v];
    float part = 0.f;
    for (int i = s + t; i < e; i += 64) {
        int tt = g_idx[i] - tbase;
        float sc = ed + g_attdot[tri[3 * tt + 2]] + ab;
        sc = sc > 0.f ? sc : 0.2f * sc;
        part += expf(sc);
    }
    for (int o = 16; o; o >>= 1) part += __shfl_xor_sync(0xffffffffu, part, o);
    if ((t & 31) == 0) sred[t >> 5] = part;
    __syncthreads();
    if (t == 0) {
        float rs = sred[0] + sred[1];
        s_inv = (rs > 0.f) ? 1.f / rs : 0.f;
    }
    __syncthreads();
    float inv_rs = s_inv;
    float acc[8] = {0.f, 0.f, 0.f, 0.f, 0.f, 0.f, 0.f, 0.f};
    const __half* table = half_id ? g_valW : g_attW;
    const int* sh_row = half_id ? sh_val : sh_att;
    for (int base = s; base < e; base += 64) {
        int cnt = min(64, e - base);
        if (t < cnt) {
            int tt = g_idx[base + t] - tbase;
            sh_att[t] = tri[3 * tt + 2];
            sh_val[t] = tri[3 * tt + 1];
            float sc = ed + g_attdot[sh_att[t]] + ab;
            sc = sc > 0.f ? sc : 0.2f * sc;
            sh_p[t] = expf(sc) * inv_rs;
        }
        __syncthreads();
        int j = 0;
        for (; j + 3 < cnt; j += 4) {
            uint4 u0 = *(const uint4*)&table[(size_t)sh_row[j + 0] * DIM + ld];
            uint4 u1 = *(const uint4*)&table[(size_t)sh_row[j + 1] * DIM + ld];
            uint4 u2 = *(const uint4*)&table[(size_t)sh_row[j + 2] * DIM + ld];
            uint4 u3 = *(const uint4*)&table[(size_t)sh_row[j + 3] * DIM + ld];
            acc_u4(acc, u0, sh_p[j + 0]);
            acc_u4(acc, u1, sh_p[j + 1]);
            acc_u4(acc, u2, sh_p[j + 2]);
            acc_u4(acc, u3, sh_p[j + 3]);
        }
        for (; j < cnt; j++) {
            uint4 u = *(const uint4*)&table[(size_t)sh_row[j] * DIM + ld];
            acc_u4(acc, u, sh_p[j]);
        }
        __syncthreads();
    }
    if (half_id == 1) {
        #pragma unroll
        for (int q = 0; q < 8; q++) sh_acc[t & 31][q] = acc[q];
    }
    __syncthreads();
    if (half_id == 0) {
        const float* ef_row = side ? ent1 + (size_t)(v - n0) * DIM : ent0 + (size_t)v * DIM;
        float4 e0 = *(const float4*)&ef_row[ld];
        float4 e1 = *(const float4*)&ef_row[ld + 4];
        float ef[8] = {e0.x, e0.y, e0.z, e0.w, e1.x, e1.y, e1.z, e1.w};
        float outv[8];
        __half h8[8];
        #pragma unroll
        for (int q = 0; q < 8; q++) {
            float x = acc[q] + sh_acc[t][q] + ef[q];
            x = x > 0.f ? x : expm1f(x);
            outv[q] = x;
            h8[q] = __float2half(x);
        }
        *(float4*)&g_F1[(size_t)v * DIM + ld]     = make_float4(outv[0], outv[1], outv[2], outv[3]);
        *(float4*)&g_F1[(size_t)v * DIM + ld + 4] = make_float4(outv[4], outv[5], outv[6], outv[7]);
        *(uint4*)&g_Fh[(size_t)v * DIM + ld] = *(uint4*)h8;
    }
}
// GCN mean-agg: warp-halves alternate neighbors, 4x unrolled uint4 loads
__global__ void gcn_agg_h_k(const int* __restrict__ c0, const int* __restrict__ c1,
                            int E0, int n0, __half* __restrict__ outh) {
    int v = blockIdx.x;
    int t = threadIdx.x;
    int half_id = t >> 5;
    int ld = (t & 31) * 8;
    int s = g_eptr[v], e = g_eptr[v + 1];
    __shared__ int sh_c[64];
    __shared__ float sh_acc[32][8];
    float acc[8] = {0.f, 0.f, 0.f, 0.f, 0.f, 0.f, 0.f, 0.f};
    for (int base = s; base < e; base += 64) {
        int cnt = min(64, e - base);
        if (t < cnt) {
            int i = base + t;
            sh_c[t] = (i < E0) ? c0[i] : n0 + c1[i - E0];
        }
        __syncthreads();
        int j = half_id;
        for (; j + 6 < cnt; j += 8) {
            uint4 u0 = *(const uint4*)&g_Fh[(size_t)sh_c[j + 0] * DIM + ld];
            uint4 u1 = *(const uint4*)&g_Fh[(size_t)sh_c[j + 2] * DIM + ld];
            uint4 u2 = *(const uint4*)&g_Fh[(size_t)sh_c[j + 4] * DIM + ld];
            uint4 u3 = *(const uint4*)&g_Fh[(size_t)sh_c[j + 6] * DIM + ld];
            acc_u4n(acc, u0);
            acc_u4n(acc, u1);
            acc_u4n(acc, u2);
            acc_u4n(acc, u3);
        }
        for (; j < cnt; j += 2) {
            uint4 u = *(const uint4*)&g_Fh[(size_t)sh_c[j] * DIM + ld];
            acc_u4n(acc, u);
        }
        __syncthreads();
    }
    if (half_id == 1) {
        #pragma unroll
        for (int q = 0; q < 8; q++) sh_acc[t & 31][q] = acc[q];
    }
    __syncthreads();
    if (half_id == 0) {
        float inv = (e > s) ? 1.f / (float)(e - s) : 0.f;
        __half h8[8];
        #pragma unroll
        for (int q = 0; q < 8; q++)
            h8[q] = __float2half((acc[q] + sh_acc[t][q]) * inv);
        *(uint4*)&outh[(size_t)v * DIM + ld] = *(uint4*)h8;
    }
}
__global__ void l2norm_all_k(const float* __restrict__ in, float* __restrict__ out) {
    int v = blockIdx.x;
    int t = threadIdx.x;
    __shared__ float sred[2];
    __shared__ float s_inv;
    const float4 x = *(const float4*)&in[(size_t)v * DIM + t * 4];
    float sq = x.x * x.x + x.y * x.y + x.z * x.z + x.w * x.w;
    for (int o = 16; o; o >>= 1) sq += __shfl_xor_sync(0xffffffffu, sq, o);
    if ((t & 31) == 0) sred[t >> 5] = sq;
    __syncthreads();
    if (t == 0) {
        float nrm = sqrtf(sred[0] + sred[1]);
        s_inv = 1.f / fmaxf(nrm, 1e-12f);
    }
    __syncthreads();
    float inv = s_inv;
    float4 y = make_float4(x.x * inv, x.y * inv, x.z * inv, x.w * inv);
    *(float4*)&out[(size_t)v * DIM + t * 4] = y;
}
__global__ void gather_all_k(const int* __restrict__ s0, const int* __restrict__ s1,
                             int nseed, int n0,
                             const float* __restrict__ src, float* __restrict__ dst) {
    int i = blockIdx.x;
    int t = threadIdx.x;
    int node = (i < nseed) ? s0[i] : n0 + s1[i - nseed];
    *(float4*)&dst[(size_t)i * DIM + t * 4] =
        *(const float4*)&src[(size_t)node * DIM + t * 4];
}

// ---------------- host orchestration ----------------
static inline int ceildiv(int a, int b) { return (a + b - 1) / b; }

extern "C" void kernel_launch(void* const* d_in, const int* in_sizes, int n_in,
                              void* d_out, int out_size) {
    const int* seed_sr = (const int*)d_in[0];
    const int* seed_tg = (const int*)d_in[1];
    const int* tri_sr  = (const int*)d_in[2];
    const int* tri_tg  = (const int*)d_in[3];
    const int* rows_sr = (const int*)d_in[4];
    const int* cols_sr = (const int*)d_in[5];
    const int* rows_tg = (const int*)d_in[6];
    const int* cols_tg = (const int*)d_in[7];
    const float* att_feats = (const float*)d_in[8];
    const float* val_feats = (const float*)d_in[9];
    const float* ent_sr = (const float*)d_in[10];
    const float* ent_tg = (const float*)d_in[11];
    const float* a_w   = (const float*)d_in[12];
    const float* a_b   = (const float*)d_in[13];
    const float* W_enc = (const float*)d_in[14];
    const float* w1    = (const float*)d_in[15];
    const float* b1    = (const float*)d_in[16];
    const float* w2    = (const float*)d_in[17];
    const float* b2    = (const float*)d_in[18];
    (void)n_in; (void)out_size;

    const int nseed  = in_sizes[0];
    const int ne0    = in_sizes[2] / 3;
    const int ne1    = in_sizes[3] / 3;
    const int E0     = in_sizes[4];
    const int E1     = in_sizes[6];
    const int natt   = in_sizes[8] / DIM;
    const int nval   = in_sizes[9] / 300;
    const int n0     = in_sizes[10] / DIM;
    const int n1     = in_sizes[11] / DIM;
    const int ntot   = n0 + n1;
    const int netot  = ne0 + ne1;
    const int Etot   = E0 + E1;

    static cudaStream_t s_aux = nullptr;
    static cudaEvent_t ev_fork = nullptr, ev_join = nullptr;
    if (!s_aux) {
        cudaStreamCreateWithFlags(&s_aux, cudaStreamNonBlocking);
        cudaEventCreateWithFlags(&ev_fork, cudaEventDisableTiming);
        cudaEventCreateWithFlags(&ev_join, cudaEventDisableTiming);
    }

    __half* valW; cudaGetSymbolAddress((void**)&valW, g_valW);
    float* F1;    cudaGetSymbolAddress((void**)&F1,   g_F1);
    float* F2;    cudaGetSymbolAddress((void**)&F2,   g_F2);
    __half* Fh;   cudaGetSymbolAddress((void**)&Fh,   g_Fh);
    int*   cntp;  cudaGetSymbolAddress((void**)&cntp, g_cnt);
    __half *xaH, *wet, *w1t, *w2t;
    cudaGetSymbolAddress((void**)&xaH, g_xa_h);
    cudaGetSymbolAddress((void**)&wet, g_wet);
    cudaGetSymbolAddress((void**)&w1t, g_w1t);
    cudaGetSymbolAddress((void**)&w2t, g_w2t);

    float* out = (float*)d_out;
    float* out_seed = out;
    float* out_full = out + (size_t)2 * nseed * DIM;

    // ---- precompute; valW GEMM (1-term A, fp16 out) forked to aux stream ----
    tsplit_h_k<<<ceildiv(256 * KPAD_VAL, 256), 256>>>(
        W_enc + (size_t)DIM * DIM, 300, KPAD_VAL, wet);
    cudaEventRecord(ev_fork, 0);
    cudaStreamWaitEvent(s_aux, ev_fork, 0);
    {
        dim3 grid(2, ceildiv(nval, 128));
        mma_gemm_k<0, 0, 1><<<grid, 256, 0, s_aux>>>(
            val_feats, nullptr, 300, KPAD_VAL, wet, nval, nullptr, nullptr, nullptr, valW);
    }
    cudaEventRecord(ev_join, s_aux);
    att_k<<<natt, DIM>>>(att_feats, W_enc, a_w, natt);
    tsplit_h_k<<<ceildiv(256 * 256, 256), 256>>>(w1, 256, 256, w1t);
    tsplit_h_k<<<ceildiv(256 * 256, 256), 256>>>(w2, 256, 256, w2t);
    entdot_all_k<<<ceildiv(ntot * 32, 256), 256>>>(ent_sr, ent_tg, a_w, n0, ntot);
    zero_int_k<<<ceildiv(ntot, 256), 256>>>(cntp, ntot);
    hist_tri_all_k<<<ceildiv(netot, 256), 256>>>(tri_sr, tri_tg, ne0, netot, n0);
    int nb = ceildiv(ntot, 1024);
    scan_blk_k<<<nb, 1024>>>(ntot);
    scan_mid_k<<<1, 32>>>(nb, ntot);
    scan_add_k<<<ceildiv(ntot, 256), 256>>>(ntot);
    scatter_tri_all_k<<<ceildiv(netot, 256), 256>>>(tri_sr, tri_tg, ne0, netot, n0);
    edge_ptr_all_k<<<ceildiv(Etot, 256), 256>>>(rows_sr, rows_tg, E0, Etot, n0, ntot);

    // ---- join: attr encoder needs valW ----
    cudaStreamWaitEvent(0, ev_join, 0);
    attr_agg_all_k<<<ntot, 64>>>(tri_sr, tri_tg, ne0, a_b, ent_sr, ent_tg, n0);

    // ---- stacked GCN layers (single-term fp16 A) ----
    dim3 ggrid(2, ceildiv(ntot, 128));
    gcn_agg_h_k<<<ntot, 64>>>(cols_sr, cols_tg, E0, n0, xaH);
    mma_gemm_k<1, 1, 1><<<ggrid, 256>>>(xaH, nullptr, 256, 256, w1t, ntot, b1, F1, F2, Fh);
    gcn_agg_h_k<<<ntot, 64>>>(cols_sr, cols_tg, E0, n0, xaH);
    mma_gemm_k<2, 1, 1><<<ggrid, 256>>>(xaH, nullptr, 256, 256, w2t, ntot, b2, F2, F1, nullptr);

    // ---- output ----
    l2norm_all_k<<<ntot, 64>>>(F1, out_full);
    gather_all_k<<<2 * nseed, 64>>>(seed_sr, seed_tg, nseed, n0, out_full, out_seed);
}